// round 12
// baseline (speedup 1.0000x reference)
#include <cuda_runtime.h>
#include <cuda_bf16.h>
#include <math.h>
#include <stdint.h>

#define B_   4
#define Q_   75
#define C_   640
#define M_   196
#define N_   5
#define KS_  5
#define BQ_  (B_*Q_)        // 300
#define NE_  (B_*N_ + BQ_)  // 320 entities (20 support class-means + 300 queries)
#define MT_  115            // M tiles of 128 per batch (115*128 = 14720)
#define RPB  14720          // padded query rows per batch
#define NPAD 224            // padded ms per class
#define KC   32             // K chunk (bf16)
#define KT_  (C_/KC)        // 20

// smem stage layout (bytes), row stride 80B (40 bf16) => conflict-free ldmatrix
#define ROWB   80
#define AHI_O  0
#define ALO_O  10240
#define BHI_O  20480
#define BLO_O  29440
#define STAGEB 38400
#define SMEM_BYTES (2*STAGEB)

// ---------------- scratch (static device globals; zero-initialized) --------
__device__ __nv_bfloat16 g_qn_hi[(size_t)B_*RPB*C_];   // pad rows stay 0
__device__ __nv_bfloat16 g_qn_lo[(size_t)B_*RPB*C_];
__device__ __nv_bfloat16 g_sn_hi[B_*N_*NPAD*C_];       // pad rows 196..223 stay 0
__device__ __nv_bfloat16 g_sn_lo[B_*N_*NPAD*C_];
__device__ float g_part[NE_*20*M_];                    // per-(entity, ctile, m) sumsq
__device__ float g_rinv[NE_*M_];
__device__ float g_rowmax[BQ_*N_*2*M_];
__device__ int   g_rowarg[BQ_*N_*2*M_];
__device__ float g_loss[BQ_];

// ---------------- PTX helpers ----------------------------------------------
__device__ __forceinline__ uint32_t s2u(const void* p) {
    uint32_t a;
    asm("{ .reg .u64 t; cvta.to.shared.u64 t, %1; cvt.u32.u64 %0, t; }"
        : "=r"(a) : "l"(p));
    return a;
}
__device__ __forceinline__ void cp16(uint32_t dst, const void* src) {
    asm volatile("cp.async.cg.shared.global [%0], [%1], 16;" :: "r"(dst), "l"(src));
}
__device__ __forceinline__ void ldsm4(uint32_t* r, uint32_t a) {
    asm volatile("ldmatrix.sync.aligned.m8n8.x4.shared.b16 {%0,%1,%2,%3}, [%4];"
                 : "=r"(r[0]), "=r"(r[1]), "=r"(r[2]), "=r"(r[3]) : "r"(a));
}
__device__ __forceinline__ void mma16816(float* c, const uint32_t* a, const uint32_t* b) {
    asm volatile("mma.sync.aligned.m16n8k16.row.col.f32.bf16.bf16.f32 "
                 "{%0,%1,%2,%3}, {%4,%5,%6,%7}, {%8,%9}, {%0,%1,%2,%3};"
                 : "+f"(c[0]), "+f"(c[1]), "+f"(c[2]), "+f"(c[3])
                 : "r"(a[0]), "r"(a[1]), "r"(a[2]), "r"(a[3]), "r"(b[0]), "r"(b[1]));
}

// ---------------- P0: per-(entity, ctile) partial sumsq ---------------------
__global__ void __launch_bounds__(256)
part_sumsq(const float* __restrict__ sup, const float* __restrict__ qf) {
    int tc = blockIdx.x;                 // 0..19 channel tile
    int e  = blockIdx.y;                 // 0..319 entity
    int tid = threadIdx.x;
    __shared__ float tile[32][201];      // padded: conflict-free columns

    if (e < B_*N_) {                     // support class-mean tile
        const float* base = sup + (size_t)e * KS_ * C_ * M_;
        for (int idx = tid; idx < 32*M_; idx += 256) {
            int cc = idx / M_, m = idx - cc*M_;
            float v = 0.f;
            #pragma unroll
            for (int k = 0; k < KS_; k++)
                v += base[(size_t)k*C_*M_ + (size_t)(tc*32 + cc)*M_ + m];
            tile[cc][m] = v * 0.2f;
        }
    } else {                             // query tile
        const float* in = qf + (size_t)(e - B_*N_) * C_ * M_;
        for (int idx = tid; idx < 32*M_; idx += 256) {
            int cc = idx / M_, m = idx - cc*M_;
            tile[cc][m] = in[(size_t)(tc*32 + cc)*M_ + m];
        }
    }
    __syncthreads();
    if (tid < M_) {
        float s = 0.f;
        #pragma unroll
        for (int cc = 0; cc < 32; cc++) { float v = tile[cc][tid]; s += v*v; }
        g_part[(e*20 + tc)*M_ + tid] = s;
    }
}

// ---------------- P1: fold 20 partials -> rinv ------------------------------
__global__ void rinv_k() {
    int e = blockIdx.x;
    int m = threadIdx.x;
    if (m < M_) {
        float s = 0.f;
        #pragma unroll
        for (int tc = 0; tc < 20; tc++) s += g_part[(e*20 + tc)*M_ + m];
        g_rinv[e*M_ + m] = 1.0f / fmaxf(sqrtf(s), 1e-8f);
    }
}

// ---------------- TR: transpose + scale + split (support & query) -----------
__global__ void __launch_bounds__(256)
tr_all(const float* __restrict__ sup, const float* __restrict__ qf) {
    int tc = blockIdx.x;                 // 0..19
    int e  = blockIdx.y;                 // 0..319
    int tid = threadIdx.x;
    __shared__ float tile[32][201];

    if (e < B_*N_) {
        int bn = e;
        const float* base = sup + (size_t)bn * KS_ * C_ * M_;
        for (int idx = tid; idx < 32*M_; idx += 256) {
            int cc = idx / M_, m = idx - cc*M_;
            float v = 0.f;
            #pragma unroll
            for (int k = 0; k < KS_; k++)
                v += base[(size_t)k*C_*M_ + (size_t)(tc*32 + cc)*M_ + m];
            tile[cc][m] = v * 0.2f;
        }
        __syncthreads();
        size_t ob = (size_t)bn * NPAD * C_;
        const float* rv = g_rinv + e*M_;
        for (int idx = tid; idx < M_*32; idx += 256) {
            int m = idx >> 5, cc = idx & 31;     // warp: fixed m, cc 0..31
            float v = tile[cc][m] * rv[m];
            __nv_bfloat16 h = __float2bfloat16(v);
            size_t o = ob + (size_t)m*C_ + tc*32 + cc;
            g_sn_hi[o] = h;
            g_sn_lo[o] = __float2bfloat16(v - __bfloat162float(h));
        }
    } else {
        int bq = e - B_*N_;
        int b = bq / Q_, q = bq % Q_;
        const float* in = qf + (size_t)bq * C_ * M_;
        for (int idx = tid; idx < 32*M_; idx += 256) {
            int cc = idx / M_, m = idx - cc*M_;
            tile[cc][m] = in[(size_t)(tc*32 + cc)*M_ + m];
        }
        __syncthreads();
        size_t rowbase = (size_t)b * RPB + (size_t)q * M_;
        const float* rv = g_rinv + e*M_;
        for (int idx = tid; idx < M_*32; idx += 256) {
            int m = idx >> 5, cc = idx & 31;
            float v = tile[cc][m] * rv[m];
            __nv_bfloat16 h = __float2bfloat16(v);
            size_t o = (rowbase + m)*C_ + tc*32 + cc;
            g_qn_hi[o] = h;
            g_qn_lo[o] = __float2bfloat16(v - __bfloat162float(h));
        }
    }
}

// ---------------- HMMA GEMM (split-bf16 x3) + row max/argmax epilogue -------
// CTA: tile 128(mq) x 112(ms) per (b, mtile, class, half). 8 warps 4x2,
// warp tile 32x56. Double-buffered cp.async, K chunks of 32.
// R12: hoisted cp.async/ldsm addressing; B loaded via ldsm.x4 (both k-halves
// in one op). MMA order per accumulator identical to the validated kernel.
__global__ void __launch_bounds__(256, 2)
gemm_hmma() {
    int nh = blockIdx.x;             // n*2 + half  (fastest: A-tile L2 reuse)
    int n = nh >> 1, half = nh & 1;
    int mt = blockIdx.y, b = blockIdx.z;

    extern __shared__ char dynsm[];
    uint32_t sbase = s2u(dynsm);

    int tid = threadIdx.x, lane = tid & 31, wid = tid >> 5;
    int wr = wid >> 1, wc = wid & 1;

    const size_t arbase = (size_t)b * RPB + (size_t)mt * 128;
    const size_t brbase = (size_t)(b*N_ + n) * NPAD + (size_t)half * 112;

    // ---- hoisted cp.async addressing (per-thread, loop-invariant) ----
    // A: 512 chunk-slots over 256 threads (2 each); B: 448 (1 + maybe 1)
    int itA0 = tid,        rA0 = itA0 >> 2, cA0 = itA0 & 3;
    int itA1 = tid + 256,  rA1 = itA1 >> 2, cA1 = itA1 & 3;
    const size_t gA0 = (arbase + rA0) * C_ + cA0*8;
    const size_t gA1 = (arbase + rA1) * C_ + cA1*8;
    const uint32_t dA0 = rA0*ROWB + cA0*16;
    const uint32_t dA1 = rA1*ROWB + cA1*16;
    int itB0 = tid,        rB0 = itB0 >> 2, cB0 = itB0 & 3;
    int itB1 = tid + 256,  rB1 = itB1 >> 2, cB1 = itB1 & 3;
    const size_t gB0 = (brbase + rB0) * C_ + cB0*8;
    const size_t gB1 = (brbase + rB1) * C_ + cB1*8;
    const uint32_t dB0 = rB0*ROWB + cB0*16;
    const uint32_t dB1 = rB1*ROWB + cB1*16;
    const bool hasB1 = (tid < 192);

    auto issue = [&](int stage, int kt) {
        uint32_t so = sbase + stage * STAGEB;
        int ko = kt * KC;
        cp16(so + AHI_O + dA0, g_qn_hi + gA0 + ko);
        cp16(so + ALO_O + dA0, g_qn_lo + gA0 + ko);
        cp16(so + AHI_O + dA1, g_qn_hi + gA1 + ko);
        cp16(so + ALO_O + dA1, g_qn_lo + gA1 + ko);
        cp16(so + BHI_O + dB0, g_sn_hi + gB0 + ko);
        cp16(so + BLO_O + dB0, g_sn_lo + gB0 + ko);
        if (hasB1) {
            cp16(so + BHI_O + dB1, g_sn_hi + gB1 + ko);
            cp16(so + BLO_O + dB1, g_sn_lo + gB1 + ko);
        }
        asm volatile("cp.async.commit_group;" ::: "memory");
    };

    // ---- hoisted ldsm lane offsets ----
    // A (x4 per (i,ks)): lane L addresses row of its 8x8 matrix
    uint32_t aoff[2][2];
    {
        int arow = (lane & 7) + ((lane >> 3) & 1) * 8;
        int acolb = ((lane >> 4) & 1) * 16;           // bytes
        #pragma unroll
        for (int i = 0; i < 2; i++)
            #pragma unroll
            for (int ks = 0; ks < 2; ks++)
                aoff[i][ks] = (uint32_t)((wr*32 + i*16 + arow)*ROWB + ks*32 + acolb);
    }
    // B (x4 per j, both ks): quad = lane>>3 -> (ks = quad>>1, khalf = quad&1)
    const uint32_t boff0 = (uint32_t)((wc*56 + (lane & 7))*ROWB
                          + ((lane >> 4) & 1)*32 + ((lane >> 3) & 1)*16);

    float acc[2][7][4];
    #pragma unroll
    for (int i = 0; i < 2; i++)
        #pragma unroll
        for (int j = 0; j < 7; j++)
            #pragma unroll
            for (int p = 0; p < 4; p++) acc[i][j][p] = 0.f;

    issue(0, 0);

    #pragma unroll 1
    for (int kt = 0; kt < KT_; kt++) {
        if (kt + 1 < KT_) {
            issue((kt + 1) & 1, kt + 1);
            asm volatile("cp.async.wait_group 1;" ::: "memory");
        } else {
            asm volatile("cp.async.wait_group 0;" ::: "memory");
        }
        __syncthreads();

        uint32_t so = sbase + (kt & 1) * STAGEB;

        uint32_t Ahi[2][2][4], Alo[2][2][4];
        #pragma unroll
        for (int i = 0; i < 2; i++)
            #pragma unroll
            for (int ks = 0; ks < 2; ks++) {
                ldsm4(Ahi[i][ks], so + AHI_O + aoff[i][ks]);
                ldsm4(Alo[i][ks], so + ALO_O + aoff[i][ks]);
            }

        #pragma unroll
        for (int j = 0; j < 7; j++) {
            uint32_t B4h[4], B4l[4];                  // [ks*2 + khalf]
            uint32_t bj = so + boff0 + j*(8*ROWB);
            ldsm4(B4h, bj + BHI_O);
            ldsm4(B4l, bj + BLO_O);
            #pragma unroll
            for (int ks = 0; ks < 2; ks++)
                #pragma unroll
                for (int i = 0; i < 2; i++) {
                    mma16816(acc[i][j], Ahi[i][ks], &B4h[ks*2]);
                    mma16816(acc[i][j], Ahi[i][ks], &B4l[ks*2]);
                    mma16816(acc[i][j], Alo[i][ks], &B4h[ks*2]);
                }
        }
        __syncthreads();
    }

    // ---- epilogue: per-row max/argmax (first-occurrence ties) ----
    float* sv = (float*)dynsm;            // [2][128]
    int*   sc = (int*)(dynsm + 1024);     // [2][128]

    int rq = lane >> 2, cq = lane & 3;
    #pragma unroll
    for (int i = 0; i < 2; i++) {
        #pragma unroll
        for (int rh = 0; rh < 2; rh++) {
            float bv = -1e30f; int bc = 0x7fffffff;
            #pragma unroll
            for (int j = 0; j < 7; j++) {
                #pragma unroll
                for (int p = 0; p < 2; p++) {
                    int gc = half*112 + wc*56 + j*8 + cq*2 + p;
                    float v = acc[i][j][rh*2 + p];
                    if (gc < M_ && (v > bv || (v == bv && gc < bc))) { bv = v; bc = gc; }
                }
            }
            #pragma unroll
            for (int off = 1; off < 4; off <<= 1) {
                float ov = __shfl_xor_sync(0xffffffffu, bv, off);
                int   oc = __shfl_xor_sync(0xffffffffu, bc, off);
                if (ov > bv || (ov == bv && oc < bc)) { bv = ov; bc = oc; }
            }
            if (cq == 0) {
                int rl = wr*32 + i*16 + rh*8 + rq;      // CTA-local row 0..127
                sv[wc*128 + rl] = bv;
                sc[wc*128 + rl] = bc;
            }
        }
    }
    __syncthreads();

    if (tid < 128) {
        float v0 = sv[tid],       v1 = sv[128 + tid];
        int   c0 = sc[tid],       c1 = sc[128 + tid];
        float bv; int bc;
        if (v1 > v0) { bv = v1; bc = c1; } else { bv = v0; bc = c0; }
        int gr = mt*128 + tid;
        if (gr < Q_*M_) {
            int q = gr / M_, mq = gr % M_;
            int o = (((b*Q_ + q)*N_ + n)*2 + half)*M_ + mq;
            g_rowmax[o] = bv;
            g_rowarg[o] = bc;
        }
    }
}

// ---------------- per-(b,q) mutual-NN mask + predict + loss -----------------
__global__ void combine_kernel(const int* __restrict__ qy) {
    int bq = blockIdx.x;
    int tid = threadIdx.x;          // 256 threads

    __shared__ float rowm[N_][M_];
    __shared__ float bestv[M_];
    __shared__ int   bestj[M_];
    __shared__ int   maskf[M_];
    __shared__ float pred[N_];

    if (tid < M_) {
        float bv = -1e30f; int bj = 0;
        #pragma unroll
        for (int nn = 0; nn < N_; nn++) {
            int o0 = ((bq*N_ + nn)*2 + 0)*M_ + tid;
            int o1 = ((bq*N_ + nn)*2 + 1)*M_ + tid;
            float m0 = g_rowmax[o0]; int a0 = g_rowarg[o0];
            float m1 = g_rowmax[o1]; int a1 = g_rowarg[o1];
            float rv; int ra;
            if (m1 > m0) { rv = m1; ra = a1; } else { rv = m0; ra = a0; }
            rowm[nn][tid] = rv;
            if (rv > bv) { bv = rv; bj = nn*M_ + ra; }   // ascending n: first occurrence
        }
        bestv[tid] = bv; bestj[tid] = bj;
    }
    __syncthreads();

    if (tid < M_) {
        float v = bestv[tid]; int j = bestj[tid];
        int ok = (v + 1.0f) > 0.0f;
        for (int t = 0; t < M_; t++) {
            if (t == tid) continue;
            if (bestj[t] == j) {
                float vt = bestv[t];
                if (vt > v || (vt == v && t < tid)) ok = 0;
            }
        }
        maskf[tid] = ok;
    }
    __syncthreads();

    if (tid < N_) {                 // deterministic fixed-order sum
        float s = 0.f;
        for (int m = 0; m < M_; m++)
            if (maskf[m]) s += rowm[tid][m];
        pred[tid] = 2.0f * s;       // TEMPERATURE
    }
    __syncthreads();

    if (tid == 0) {
        float mx = pred[0];
        #pragma unroll
        for (int nn = 1; nn < N_; nn++) mx = fmaxf(mx, pred[nn]);
        float se = 0.f;
        #pragma unroll
        for (int nn = 0; nn < N_; nn++) se += expf(pred[nn] - mx);
        float lse = mx + logf(se);
        int y = qy[bq];
        g_loss[bq] = lse - pred[y];
    }
}

__global__ void final_kernel(float* __restrict__ out) {
    __shared__ float part[32];
    int lane = threadIdx.x;
    float s = 0.f;
    for (int i = lane; i < BQ_; i += 32) s += g_loss[i];   // fixed ascending order
    part[lane] = s;
    __syncwarp();
    if (lane == 0) {
        float t = 0.f;
        #pragma unroll
        for (int w = 0; w < 32; w++) t += part[w];          // fixed ascending order
        out[0] = t / (float)BQ_;
    }
}

extern "C" void kernel_launch(void* const* d_in, const int* in_sizes, int n_in,
                              void* d_out, int out_size) {
    const float* sup = (const float*)d_in[0];
    // d_in[1] = support_y : unused by the reference computation
    const float* qf  = (const float*)d_in[2];
    const int*   qy  = (const int*)d_in[3];

    cudaFuncSetAttribute(gemm_hmma, cudaFuncAttributeMaxDynamicSharedMemorySize, SMEM_BYTES);

    part_sumsq<<<dim3(20, NE_), 256>>>(sup, qf);      // launch 0
    rinv_k    <<<NE_, 224>>>();                       // launch 1
    tr_all    <<<dim3(20, NE_), 256>>>(sup, qf);      // launch 2

    dim3 grid(N_*2, MT_, B_);   // nh fastest -> adjacent CTAs share A tile in L2
    gemm_hmma<<<grid, 256, SMEM_BYTES>>>();           // launch 3 (ncu slot)

    combine_kernel<<<BQ_, 256>>>(qy);
    final_kernel  <<<1, 32>>>((float*)d_out);
}

// round 13
// speedup vs baseline: 1.0128x; 1.0128x over previous
#include <cuda_runtime.h>
#include <cuda_bf16.h>
#include <math.h>
#include <stdint.h>

#define B_   4
#define Q_   75
#define C_   640
#define M_   196
#define N_   5
#define KS_  5
#define BQ_  (B_*Q_)        // 300
#define NE_  (B_*N_ + BQ_)  // 320 entities
#define MT_  230            // M tiles of 64 per batch (230*64 = 14720)
#define RPB  14720          // padded query rows per batch
#define NPAD 224            // padded ms per class
#define KC   32             // K chunk (bf16)
#define KT_  (C_/KC)        // 20
#define TPB  128            // 4 warps per CTA

// smem stage layout (bytes), row stride 80B => conflict-free ldmatrix
#define ROWB   80
#define AHI_O  0
#define ALO_O  5120
#define BHI_O  10240
#define BLO_O  19200
#define STAGEB 28160
#define SMEM_BYTES (2*STAGEB)   // 56320 per CTA; 4 CTAs/SM

// ---------------- scratch (static device globals; zero-initialized) --------
__device__ __nv_bfloat16 g_qn_hi[(size_t)B_*RPB*C_];   // pad rows stay 0
__device__ __nv_bfloat16 g_qn_lo[(size_t)B_*RPB*C_];
__device__ __nv_bfloat16 g_sn_hi[B_*N_*NPAD*C_];       // pad rows 196..223 stay 0
__device__ __nv_bfloat16 g_sn_lo[B_*N_*NPAD*C_];
__device__ float g_part[NE_*20*M_];
__device__ float g_rinv[NE_*M_];
__device__ float g_rowmax[BQ_*N_*2*M_];
__device__ int   g_rowarg[BQ_*N_*2*M_];
__device__ float g_loss[BQ_];

// ---------------- PTX helpers ----------------------------------------------
__device__ __forceinline__ uint32_t s2u(const void* p) {
    uint32_t a;
    asm("{ .reg .u64 t; cvta.to.shared.u64 t, %1; cvt.u32.u64 %0, t; }"
        : "=r"(a) : "l"(p));
    return a;
}
__device__ __forceinline__ void cp16(uint32_t dst, const void* src) {
    asm volatile("cp.async.cg.shared.global [%0], [%1], 16;" :: "r"(dst), "l"(src));
}
__device__ __forceinline__ void ldsm4(uint32_t* r, uint32_t a) {
    asm volatile("ldmatrix.sync.aligned.m8n8.x4.shared.b16 {%0,%1,%2,%3}, [%4];"
                 : "=r"(r[0]), "=r"(r[1]), "=r"(r[2]), "=r"(r[3]) : "r"(a));
}
__device__ __forceinline__ void mma16816(float* c, const uint32_t* a, const uint32_t* b) {
    asm volatile("mma.sync.aligned.m16n8k16.row.col.f32.bf16.bf16.f32 "
                 "{%0,%1,%2,%3}, {%4,%5,%6,%7}, {%8,%9}, {%0,%1,%2,%3};"
                 : "+f"(c[0]), "+f"(c[1]), "+f"(c[2]), "+f"(c[3])
                 : "r"(a[0]), "r"(a[1]), "r"(a[2]), "r"(a[3]), "r"(b[0]), "r"(b[1]));
}

// ---------------- P0: per-(entity, ctile) partial sumsq ---------------------
__global__ void __launch_bounds__(256)
part_sumsq(const float* __restrict__ sup, const float* __restrict__ qf) {
    int tc = blockIdx.x;
    int e  = blockIdx.y;
    int tid = threadIdx.x;
    __shared__ float tile[32][201];

    if (e < B_*N_) {
        const float* base = sup + (size_t)e * KS_ * C_ * M_;
        for (int idx = tid; idx < 32*M_; idx += 256) {
            int cc = idx / M_, m = idx - cc*M_;
            float v = 0.f;
            #pragma unroll
            for (int k = 0; k < KS_; k++)
                v += base[(size_t)k*C_*M_ + (size_t)(tc*32 + cc)*M_ + m];
            tile[cc][m] = v * 0.2f;
        }
    } else {
        const float* in = qf + (size_t)(e - B_*N_) * C_ * M_;
        for (int idx = tid; idx < 32*M_; idx += 256) {
            int cc = idx / M_, m = idx - cc*M_;
            tile[cc][m] = in[(size_t)(tc*32 + cc)*M_ + m];
        }
    }
    __syncthreads();
    if (tid < M_) {
        float s = 0.f;
        #pragma unroll
        for (int cc = 0; cc < 32; cc++) { float v = tile[cc][tid]; s += v*v; }
        g_part[(e*20 + tc)*M_ + tid] = s;
    }
}

// ---------------- P1: fold 20 partials -> rinv ------------------------------
__global__ void rinv_k() {
    int e = blockIdx.x;
    int m = threadIdx.x;
    if (m < M_) {
        float s = 0.f;
        #pragma unroll
        for (int tc = 0; tc < 20; tc++) s += g_part[(e*20 + tc)*M_ + m];
        g_rinv[e*M_ + m] = 1.0f / fmaxf(sqrtf(s), 1e-8f);
    }
}

// ---------------- TR: transpose + scale + split (support & query) -----------
__global__ void __launch_bounds__(256)
tr_all(const float* __restrict__ sup, const float* __restrict__ qf) {
    int tc = blockIdx.x;
    int e  = blockIdx.y;
    int tid = threadIdx.x;
    __shared__ float tile[32][201];

    if (e < B_*N_) {
        int bn = e;
        const float* base = sup + (size_t)bn * KS_ * C_ * M_;
        for (int idx = tid; idx < 32*M_; idx += 256) {
            int cc = idx / M_, m = idx - cc*M_;
            float v = 0.f;
            #pragma unroll
            for (int k = 0; k < KS_; k++)
                v += base[(size_t)k*C_*M_ + (size_t)(tc*32 + cc)*M_ + m];
            tile[cc][m] = v * 0.2f;
        }
        __syncthreads();
        size_t ob = (size_t)bn * NPAD * C_;
        const float* rv = g_rinv + e*M_;
        for (int idx = tid; idx < M_*32; idx += 256) {
            int m = idx >> 5, cc = idx & 31;
            float v = tile[cc][m] * rv[m];
            __nv_bfloat16 h = __float2bfloat16(v);
            size_t o = ob + (size_t)m*C_ + tc*32 + cc;
            g_sn_hi[o] = h;
            g_sn_lo[o] = __float2bfloat16(v - __bfloat162float(h));
        }
    } else {
        int bq = e - B_*N_;
        int b = bq / Q_, q = bq % Q_;
        const float* in = qf + (size_t)bq * C_ * M_;
        for (int idx = tid; idx < 32*M_; idx += 256) {
            int cc = idx / M_, m = idx - cc*M_;
            tile[cc][m] = in[(size_t)(tc*32 + cc)*M_ + m];
        }
        __syncthreads();
        size_t rowbase = (size_t)b * RPB + (size_t)q * M_;
        const float* rv = g_rinv + e*M_;
        for (int idx = tid; idx < M_*32; idx += 256) {
            int m = idx >> 5, cc = idx & 31;
            float v = tile[cc][m] * rv[m];
            __nv_bfloat16 h = __float2bfloat16(v);
            size_t o = (rowbase + m)*C_ + tc*32 + cc;
            g_qn_hi[o] = h;
            g_qn_lo[o] = __float2bfloat16(v - __bfloat162float(h));
        }
    }
}

// ---------------- HMMA GEMM (split-bf16 x3) + row max/argmax epilogue -------
// R13: 128-thread CTA, tile 64(mq) x 112(ms), 4 warps 2x2, warp tile 32x56.
// 4 CTAs/SM -> independent barrier phases fill the tensor pipe.
// Per-accumulator MMA order identical to the validated kernel.
__global__ void __launch_bounds__(TPB, 4)
gemm_hmma() {
    int nh = blockIdx.x;             // n*2 + half
    int n = nh >> 1, half = nh & 1;
    int mt = blockIdx.y, b = blockIdx.z;

    extern __shared__ char dynsm[];
    uint32_t sbase = s2u(dynsm);

    int tid = threadIdx.x, lane = tid & 31, wid = tid >> 5;
    int wr = wid >> 1, wc = wid & 1;     // 2 x 2 warp grid

    const size_t arbase = (size_t)b * RPB + (size_t)mt * 64;
    const size_t brbase = (size_t)(b*N_ + n) * NPAD + (size_t)half * 112;

    // ---- hoisted cp.async addressing ----
    // A: 64 rows x 4 chunks = 256 slots / 128 thr = 2 each
    int rA0 = tid >> 2,          cA0 = tid & 3;
    int itA1 = tid + 128;
    int rA1 = itA1 >> 2,         cA1 = itA1 & 3;
    const size_t gA0 = (arbase + rA0) * C_ + cA0*8;
    const size_t gA1 = (arbase + rA1) * C_ + cA1*8;
    const uint32_t dA0 = rA0*ROWB + cA0*16;
    const uint32_t dA1 = rA1*ROWB + cA1*16;
    // B: 112 rows x 4 chunks = 448 slots -> 3 each + threads<64 a 4th
    int rB0 = tid >> 2,          cB0 = tid & 3;
    int itB1 = tid + 128;
    int rB1 = itB1 >> 2,         cB1 = itB1 & 3;
    int itB2 = tid + 256;
    int rB2 = itB2 >> 2,         cB2 = itB2 & 3;
    int itB3 = tid + 384;
    int rB3 = itB3 >> 2,         cB3 = itB3 & 3;
    const size_t gB0 = (brbase + rB0) * C_ + cB0*8;
    const size_t gB1 = (brbase + rB1) * C_ + cB1*8;
    const size_t gB2 = (brbase + rB2) * C_ + cB2*8;
    const size_t gB3 = (brbase + rB3) * C_ + cB3*8;
    const uint32_t dB0 = rB0*ROWB + cB0*16;
    const uint32_t dB1 = rB1*ROWB + cB1*16;
    const uint32_t dB2 = rB2*ROWB + cB2*16;
    const uint32_t dB3 = rB3*ROWB + cB3*16;
    const bool hasB3 = (tid < 64);

    auto issue = [&](int stage, int kt) {
        uint32_t so = sbase + stage * STAGEB;
        int ko = kt * KC;
        cp16(so + AHI_O + dA0, g_qn_hi + gA0 + ko);
        cp16(so + ALO_O + dA0, g_qn_lo + gA0 + ko);
        cp16(so + AHI_O + dA1, g_qn_hi + gA1 + ko);
        cp16(so + ALO_O + dA1, g_qn_lo + gA1 + ko);
        cp16(so + BHI_O + dB0, g_sn_hi + gB0 + ko);
        cp16(so + BLO_O + dB0, g_sn_lo + gB0 + ko);
        cp16(so + BHI_O + dB1, g_sn_hi + gB1 + ko);
        cp16(so + BLO_O + dB1, g_sn_lo + gB1 + ko);
        cp16(so + BHI_O + dB2, g_sn_hi + gB2 + ko);
        cp16(so + BLO_O + dB2, g_sn_lo + gB2 + ko);
        if (hasB3) {
            cp16(so + BHI_O + dB3, g_sn_hi + gB3 + ko);
            cp16(so + BLO_O + dB3, g_sn_lo + gB3 + ko);
        }
        asm volatile("cp.async.commit_group;" ::: "memory");
    };

    // ---- hoisted ldsm lane offsets ----
    uint32_t aoff[2][2];
    {
        int arow = (lane & 7) + ((lane >> 3) & 1) * 8;
        int acolb = ((lane >> 4) & 1) * 16;
        #pragma unroll
        for (int i = 0; i < 2; i++)
            #pragma unroll
            for (int ks = 0; ks < 2; ks++)
                aoff[i][ks] = (uint32_t)((wr*32 + i*16 + arow)*ROWB + ks*32 + acolb);
    }
    const uint32_t boff0 = (uint32_t)((wc*56 + (lane & 7))*ROWB
                          + ((lane >> 4) & 1)*32 + ((lane >> 3) & 1)*16);

    float acc[2][7][4];
    #pragma unroll
    for (int i = 0; i < 2; i++)
        #pragma unroll
        for (int j = 0; j < 7; j++)
            #pragma unroll
            for (int p = 0; p < 4; p++) acc[i][j][p] = 0.f;

    issue(0, 0);

    #pragma unroll 1
    for (int kt = 0; kt < KT_; kt++) {
        if (kt + 1 < KT_) {
            issue((kt + 1) & 1, kt + 1);
            asm volatile("cp.async.wait_group 1;" ::: "memory");
        } else {
            asm volatile("cp.async.wait_group 0;" ::: "memory");
        }
        __syncthreads();

        uint32_t so = sbase + (kt & 1) * STAGEB;

        uint32_t Ahi[2][2][4], Alo[2][2][4];
        #pragma unroll
        for (int i = 0; i < 2; i++)
            #pragma unroll
            for (int ks = 0; ks < 2; ks++) {
                ldsm4(Ahi[i][ks], so + AHI_O + aoff[i][ks]);
                ldsm4(Alo[i][ks], so + ALO_O + aoff[i][ks]);
            }

        #pragma unroll
        for (int j = 0; j < 7; j++) {
            uint32_t B4h[4], B4l[4];                  // [ks*2 + khalf]
            uint32_t bj = so + boff0 + j*(8*ROWB);
            ldsm4(B4h, bj + BHI_O);
            ldsm4(B4l, bj + BLO_O);
            #pragma unroll
            for (int ks = 0; ks < 2; ks++)
                #pragma unroll
                for (int i = 0; i < 2; i++) {
                    mma16816(acc[i][j], Ahi[i][ks], &B4h[ks*2]);
                    mma16816(acc[i][j], Ahi[i][ks], &B4l[ks*2]);
                    mma16816(acc[i][j], Alo[i][ks], &B4h[ks*2]);
                }
        }
        __syncthreads();
    }

    // ---- epilogue: per-row max/argmax (first-occurrence ties) ----
    float* sv = (float*)dynsm;            // [2][64]
    int*   sc = (int*)(dynsm + 512);      // [2][64]

    int rq = lane >> 2, cq = lane & 3;
    #pragma unroll
    for (int i = 0; i < 2; i++) {
        #pragma unroll
        for (int rh = 0; rh < 2; rh++) {
            float bv = -1e30f; int bc = 0x7fffffff;
            #pragma unroll
            for (int j = 0; j < 7; j++) {
                #pragma unroll
                for (int p = 0; p < 2; p++) {
                    int gc = half*112 + wc*56 + j*8 + cq*2 + p;
                    float v = acc[i][j][rh*2 + p];
                    if (gc < M_ && (v > bv || (v == bv && gc < bc))) { bv = v; bc = gc; }
                }
            }
            #pragma unroll
            for (int off = 1; off < 4; off <<= 1) {
                float ov = __shfl_xor_sync(0xffffffffu, bv, off);
                int   oc = __shfl_xor_sync(0xffffffffu, bc, off);
                if (ov > bv || (ov == bv && oc < bc)) { bv = ov; bc = oc; }
            }
            if (cq == 0) {
                int rl = wr*32 + i*16 + rh*8 + rq;      // CTA-local row 0..63
                sv[wc*64 + rl] = bv;
                sc[wc*64 + rl] = bc;
            }
        }
    }
    __syncthreads();

    if (tid < 64) {
        float v0 = sv[tid],      v1 = sv[64 + tid];
        int   c0 = sc[tid],      c1 = sc[64 + tid];
        float bv; int bc;
        if (v1 > v0) { bv = v1; bc = c1; } else { bv = v0; bc = c0; }
        int gr = mt*64 + tid;
        if (gr < Q_*M_) {
            int q = gr / M_, mq = gr % M_;
            int o = (((b*Q_ + q)*N_ + n)*2 + half)*M_ + mq;
            g_rowmax[o] = bv;
            g_rowarg[o] = bc;
        }
    }
}

// ---------------- per-(b,q) mutual-NN mask + predict + loss -----------------
__global__ void combine_kernel(const int* __restrict__ qy) {
    int bq = blockIdx.x;
    int tid = threadIdx.x;          // 256 threads

    __shared__ float rowm[N_][M_];
    __shared__ float bestv[M_];
    __shared__ int   bestj[M_];
    __shared__ int   maskf[M_];
    __shared__ float pred[N_];

    if (tid < M_) {
        float bv = -1e30f; int bj = 0;
        #pragma unroll
        for (int nn = 0; nn < N_; nn++) {
            int o0 = ((bq*N_ + nn)*2 + 0)*M_ + tid;
            int o1 = ((bq*N_ + nn)*2 + 1)*M_ + tid;
            float m0 = g_rowmax[o0]; int a0 = g_rowarg[o0];
            float m1 = g_rowmax[o1]; int a1 = g_rowarg[o1];
            float rv; int ra;
            if (m1 > m0) { rv = m1; ra = a1; } else { rv = m0; ra = a0; }
            rowm[nn][tid] = rv;
            if (rv > bv) { bv = rv; bj = nn*M_ + ra; }
        }
        bestv[tid] = bv; bestj[tid] = bj;
    }
    __syncthreads();

    if (tid < M_) {
        float v = bestv[tid]; int j = bestj[tid];
        int ok = (v + 1.0f) > 0.0f;
        for (int t = 0; t < M_; t++) {
            if (t == tid) continue;
            if (bestj[t] == j) {
                float vt = bestv[t];
                if (vt > v || (vt == v && t < tid)) ok = 0;
            }
        }
        maskf[tid] = ok;
    }
    __syncthreads();

    if (tid < N_) {
        float s = 0.f;
        for (int m = 0; m < M_; m++)
            if (maskf[m]) s += rowm[tid][m];
        pred[tid] = 2.0f * s;       // TEMPERATURE
    }
    __syncthreads();

    if (tid == 0) {
        float mx = pred[0];
        #pragma unroll
        for (int nn = 1; nn < N_; nn++) mx = fmaxf(mx, pred[nn]);
        float se = 0.f;
        #pragma unroll
        for (int nn = 0; nn < N_; nn++) se += expf(pred[nn] - mx);
        float lse = mx + logf(se);
        int y = qy[bq];
        g_loss[bq] = lse - pred[y];
    }
}

__global__ void final_kernel(float* __restrict__ out) {
    __shared__ float part[32];
    int lane = threadIdx.x;
    float s = 0.f;
    for (int i = lane; i < BQ_; i += 32) s += g_loss[i];
    part[lane] = s;
    __syncwarp();
    if (lane == 0) {
        float t = 0.f;
        #pragma unroll
        for (int w = 0; w < 32; w++) t += part[w];
        out[0] = t / (float)BQ_;
    }
}

extern "C" void kernel_launch(void* const* d_in, const int* in_sizes, int n_in,
                              void* d_out, int out_size) {
    const float* sup = (const float*)d_in[0];
    // d_in[1] = support_y : unused by the reference computation
    const float* qf  = (const float*)d_in[2];
    const int*   qy  = (const int*)d_in[3];

    cudaFuncSetAttribute(gemm_hmma, cudaFuncAttributeMaxDynamicSharedMemorySize, SMEM_BYTES);

    part_sumsq<<<dim3(20, NE_), 256>>>(sup, qf);      // launch 0
    rinv_k    <<<NE_, 224>>>();                       // launch 1
    tr_all    <<<dim3(20, NE_), 256>>>(sup, qf);      // launch 2

    dim3 grid(N_*2, MT_, B_);   // nh fastest -> A-tile L2 reuse
    gemm_hmma<<<grid, TPB, SMEM_BYTES>>>();           // launch 3 (ncu slot)

    combine_kernel<<<BQ_, 256>>>(qy);
    final_kernel  <<<1, 32>>>((float*)d_out);
}

// round 14
// speedup vs baseline: 1.0170x; 1.0042x over previous
#include <cuda_runtime.h>
#include <cuda_bf16.h>
#include <math.h>
#include <stdint.h>

#define B_   4
#define Q_   75
#define C_   640
#define M_   196
#define N_   5
#define KS_  5
#define BQ_  (B_*Q_)        // 300
#define NE_  (B_*N_ + BQ_)  // 320 entities
#define MT_  230            // M tiles of 64 per batch (230*64 = 14720)
#define RPB  14720          // padded query rows per batch
#define NPAD 224            // padded ms per class
#define KC   32             // K chunk (bf16)
#define KT_  (C_/KC)        // 20
#define TPB  128            // 4 warps per CTA

// smem stage layout (bytes), row stride 80B => conflict-free ldmatrix
#define ROWB   80
#define AHI_O  0
#define ALO_O  5120
#define BHI_O  10240
#define BLO_O  19200
#define STAGEB 28160
#define SMEM_BYTES (2*STAGEB)   // 56320 per CTA; 4 CTAs/SM

// ---------------- scratch (static device globals; zero-initialized) --------
__device__ __nv_bfloat16 g_qn_hi[(size_t)B_*RPB*C_];   // pad rows stay 0
__device__ __nv_bfloat16 g_qn_lo[(size_t)B_*RPB*C_];
__device__ __nv_bfloat16 g_sn_hi[B_*N_*NPAD*C_];       // pad rows 196..223 stay 0
__device__ __nv_bfloat16 g_sn_lo[B_*N_*NPAD*C_];
__device__ float g_part[NE_*20*M_];
__device__ float g_rinv[NE_*M_];
__device__ float g_rowmax[BQ_*N_*2*M_];
__device__ int   g_rowarg[BQ_*N_*2*M_];
__device__ float g_loss[BQ_];

// ---------------- PTX helpers ----------------------------------------------
__device__ __forceinline__ uint32_t s2u(const void* p) {
    uint32_t a;
    asm("{ .reg .u64 t; cvta.to.shared.u64 t, %1; cvt.u32.u64 %0, t; }"
        : "=r"(a) : "l"(p));
    return a;
}
__device__ __forceinline__ void cp16(uint32_t dst, const void* src) {
    asm volatile("cp.async.cg.shared.global [%0], [%1], 16;" :: "r"(dst), "l"(src));
}
__device__ __forceinline__ void ldsm4(uint32_t* r, uint32_t a) {
    asm volatile("ldmatrix.sync.aligned.m8n8.x4.shared.b16 {%0,%1,%2,%3}, [%4];"
                 : "=r"(r[0]), "=r"(r[1]), "=r"(r[2]), "=r"(r[3]) : "r"(a));
}
__device__ __forceinline__ void mma16816(float* c, const uint32_t* a, const uint32_t* b) {
    asm volatile("mma.sync.aligned.m16n8k16.row.col.f32.bf16.bf16.f32 "
                 "{%0,%1,%2,%3}, {%4,%5,%6,%7}, {%8,%9}, {%0,%1,%2,%3};"
                 : "+f"(c[0]), "+f"(c[1]), "+f"(c[2]), "+f"(c[3])
                 : "r"(a[0]), "r"(a[1]), "r"(a[2]), "r"(a[3]), "r"(b[0]), "r"(b[1]));
}

// ---------------- P0: per-(entity, ctile) partial sumsq ---------------------
__global__ void __launch_bounds__(256)
part_sumsq(const float* __restrict__ sup, const float* __restrict__ qf) {
    int tc = blockIdx.x;
    int e  = blockIdx.y;
    int tid = threadIdx.x;
    __shared__ float tile[32][201];

    if (e < B_*N_) {
        const float* base = sup + (size_t)e * KS_ * C_ * M_;
        for (int idx = tid; idx < 32*M_; idx += 256) {
            int cc = idx / M_, m = idx - cc*M_;
            float v = 0.f;
            #pragma unroll
            for (int k = 0; k < KS_; k++)
                v += base[(size_t)k*C_*M_ + (size_t)(tc*32 + cc)*M_ + m];
            tile[cc][m] = v * 0.2f;
        }
    } else {
        const float* in = qf + (size_t)(e - B_*N_) * C_ * M_;
        for (int idx = tid; idx < 32*M_; idx += 256) {
            int cc = idx / M_, m = idx - cc*M_;
            tile[cc][m] = in[(size_t)(tc*32 + cc)*M_ + m];
        }
    }
    __syncthreads();
    if (tid < M_) {
        float s = 0.f;
        #pragma unroll
        for (int cc = 0; cc < 32; cc++) { float v = tile[cc][tid]; s += v*v; }
        g_part[(e*20 + tc)*M_ + tid] = s;
    }
}

// ---------------- P1: fold 20 partials -> rinv ------------------------------
__global__ void rinv_k() {
    int e = blockIdx.x;
    int m = threadIdx.x;
    if (m < M_) {
        float s = 0.f;
        #pragma unroll
        for (int tc = 0; tc < 20; tc++) s += g_part[(e*20 + tc)*M_ + m];
        g_rinv[e*M_ + m] = 1.0f / fmaxf(sqrtf(s), 1e-8f);
    }
}

// ---------------- TR: transpose + scale + split (support & query) -----------
__global__ void __launch_bounds__(256)
tr_all(const float* __restrict__ sup, const float* __restrict__ qf) {
    int tc = blockIdx.x;
    int e  = blockIdx.y;
    int tid = threadIdx.x;
    __shared__ float tile[32][201];

    if (e < B_*N_) {
        int bn = e;
        const float* base = sup + (size_t)bn * KS_ * C_ * M_;
        for (int idx = tid; idx < 32*M_; idx += 256) {
            int cc = idx / M_, m = idx - cc*M_;
            float v = 0.f;
            #pragma unroll
            for (int k = 0; k < KS_; k++)
                v += base[(size_t)k*C_*M_ + (size_t)(tc*32 + cc)*M_ + m];
            tile[cc][m] = v * 0.2f;
        }
        __syncthreads();
        size_t ob = (size_t)bn * NPAD * C_;
        const float* rv = g_rinv + e*M_;
        for (int idx = tid; idx < M_*32; idx += 256) {
            int m = idx >> 5, cc = idx & 31;
            float v = tile[cc][m] * rv[m];
            __nv_bfloat16 h = __float2bfloat16(v);
            size_t o = ob + (size_t)m*C_ + tc*32 + cc;
            g_sn_hi[o] = h;
            g_sn_lo[o] = __float2bfloat16(v - __bfloat162float(h));
        }
    } else {
        int bq = e - B_*N_;
        int b = bq / Q_, q = bq % Q_;
        const float* in = qf + (size_t)bq * C_ * M_;
        for (int idx = tid; idx < 32*M_; idx += 256) {
            int cc = idx / M_, m = idx - cc*M_;
            tile[cc][m] = in[(size_t)(tc*32 + cc)*M_ + m];
        }
        __syncthreads();
        size_t rowbase = (size_t)b * RPB + (size_t)q * M_;
        const float* rv = g_rinv + e*M_;
        for (int idx = tid; idx < M_*32; idx += 256) {
            int m = idx >> 5, cc = idx & 31;
            float v = tile[cc][m] * rv[m];
            __nv_bfloat16 h = __float2bfloat16(v);
            size_t o = (rowbase + m)*C_ + tc*32 + cc;
            g_qn_hi[o] = h;
            g_qn_lo[o] = __float2bfloat16(v - __bfloat162float(h));
        }
    }
}

// ---------------- HMMA GEMM (split-bf16 x3) + row max/argmax epilogue -------
// R14: as R13 (128-thr CTA, 64x112 tile, 4 CTAs/SM) but with register
// double-buffered B fragments: ldsm for j+1 issues BEFORE the 12 MMAs of j,
// giving each ldsm ~12 MMA issue-slots of latency cover.
// Per-accumulator MMA order identical -> bitwise-identical S.
__global__ void __launch_bounds__(TPB, 4)
gemm_hmma() {
    int nh = blockIdx.x;             // n*2 + half
    int n = nh >> 1, half = nh & 1;
    int mt = blockIdx.y, b = blockIdx.z;

    extern __shared__ char dynsm[];
    uint32_t sbase = s2u(dynsm);

    int tid = threadIdx.x, lane = tid & 31, wid = tid >> 5;
    int wr = wid >> 1, wc = wid & 1;     // 2 x 2 warp grid

    const size_t arbase = (size_t)b * RPB + (size_t)mt * 64;
    const size_t brbase = (size_t)(b*N_ + n) * NPAD + (size_t)half * 112;

    // ---- hoisted cp.async addressing ----
    int rA0 = tid >> 2,          cA0 = tid & 3;
    int itA1 = tid + 128;
    int rA1 = itA1 >> 2,         cA1 = itA1 & 3;
    const size_t gA0 = (arbase + rA0) * C_ + cA0*8;
    const size_t gA1 = (arbase + rA1) * C_ + cA1*8;
    const uint32_t dA0 = rA0*ROWB + cA0*16;
    const uint32_t dA1 = rA1*ROWB + cA1*16;
    int rB0 = tid >> 2,          cB0 = tid & 3;
    int itB1 = tid + 128;
    int rB1 = itB1 >> 2,         cB1 = itB1 & 3;
    int itB2 = tid + 256;
    int rB2 = itB2 >> 2,         cB2 = itB2 & 3;
    int itB3 = tid + 384;
    int rB3 = itB3 >> 2,         cB3 = itB3 & 3;
    const size_t gB0 = (brbase + rB0) * C_ + cB0*8;
    const size_t gB1 = (brbase + rB1) * C_ + cB1*8;
    const size_t gB2 = (brbase + rB2) * C_ + cB2*8;
    const size_t gB3 = (brbase + rB3) * C_ + cB3*8;
    const uint32_t dB0 = rB0*ROWB + cB0*16;
    const uint32_t dB1 = rB1*ROWB + cB1*16;
    const uint32_t dB2 = rB2*ROWB + cB2*16;
    const uint32_t dB3 = rB3*ROWB + cB3*16;
    const bool hasB3 = (tid < 64);

    auto issue = [&](int stage, int kt) {
        uint32_t so = sbase + stage * STAGEB;
        int ko = kt * KC;
        cp16(so + AHI_O + dA0, g_qn_hi + gA0 + ko);
        cp16(so + ALO_O + dA0, g_qn_lo + gA0 + ko);
        cp16(so + AHI_O + dA1, g_qn_hi + gA1 + ko);
        cp16(so + ALO_O + dA1, g_qn_lo + gA1 + ko);
        cp16(so + BHI_O + dB0, g_sn_hi + gB0 + ko);
        cp16(so + BLO_O + dB0, g_sn_lo + gB0 + ko);
        cp16(so + BHI_O + dB1, g_sn_hi + gB1 + ko);
        cp16(so + BLO_O + dB1, g_sn_lo + gB1 + ko);
        cp16(so + BHI_O + dB2, g_sn_hi + gB2 + ko);
        cp16(so + BLO_O + dB2, g_sn_lo + gB2 + ko);
        if (hasB3) {
            cp16(so + BHI_O + dB3, g_sn_hi + gB3 + ko);
            cp16(so + BLO_O + dB3, g_sn_lo + gB3 + ko);
        }
        asm volatile("cp.async.commit_group;" ::: "memory");
    };

    // ---- hoisted ldsm lane offsets ----
    uint32_t aoff[2][2];
    {
        int arow = (lane & 7) + ((lane >> 3) & 1) * 8;
        int acolb = ((lane >> 4) & 1) * 16;
        #pragma unroll
        for (int i = 0; i < 2; i++)
            #pragma unroll
            for (int ks = 0; ks < 2; ks++)
                aoff[i][ks] = (uint32_t)((wr*32 + i*16 + arow)*ROWB + ks*32 + acolb);
    }
    const uint32_t boff0 = (uint32_t)((wc*56 + (lane & 7))*ROWB
                          + ((lane >> 4) & 1)*32 + ((lane >> 3) & 1)*16);

    float acc[2][7][4];
    #pragma unroll
    for (int i = 0; i < 2; i++)
        #pragma unroll
        for (int j = 0; j < 7; j++)
            #pragma unroll
            for (int p = 0; p < 4; p++) acc[i][j][p] = 0.f;

    issue(0, 0);

    #pragma unroll 1
    for (int kt = 0; kt < KT_; kt++) {
        if (kt + 1 < KT_) {
            issue((kt + 1) & 1, kt + 1);
            asm volatile("cp.async.wait_group 1;" ::: "memory");
        } else {
            asm volatile("cp.async.wait_group 0;" ::: "memory");
        }
        __syncthreads();

        uint32_t so = sbase + (kt & 1) * STAGEB;

        // A fragments (all) + B fragment j=0 into buffer 0
        uint32_t Ahi[2][2][4], Alo[2][2][4];
        #pragma unroll
        for (int i = 0; i < 2; i++)
            #pragma unroll
            for (int ks = 0; ks < 2; ks++) {
                ldsm4(Ahi[i][ks], so + AHI_O + aoff[i][ks]);
                ldsm4(Alo[i][ks], so + ALO_O + aoff[i][ks]);
            }

        uint32_t B4h[2][4], B4l[2][4];           // double buffer [buf][ks*2+kh]
        ldsm4(B4h[0], so + boff0 + BHI_O);
        ldsm4(B4l[0], so + boff0 + BLO_O);

        #pragma unroll
        for (int j = 0; j < 7; j++) {
            int cur = j & 1;
            if (j < 6) {                          // prefetch j+1 BEFORE MMAs
                uint32_t bj = so + boff0 + (j+1)*(8*ROWB);
                ldsm4(B4h[cur ^ 1], bj + BHI_O);
                ldsm4(B4l[cur ^ 1], bj + BLO_O);
            }
            #pragma unroll
            for (int ks = 0; ks < 2; ks++)
                #pragma unroll
                for (int i = 0; i < 2; i++) {
                    mma16816(acc[i][j], Ahi[i][ks], &B4h[cur][ks*2]);
                    mma16816(acc[i][j], Ahi[i][ks], &B4l[cur][ks*2]);
                    mma16816(acc[i][j], Alo[i][ks], &B4h[cur][ks*2]);
                }
        }
        __syncthreads();
    }

    // ---- epilogue: per-row max/argmax (first-occurrence ties) ----
    float* sv = (float*)dynsm;            // [2][64]
    int*   sc = (int*)(dynsm + 512);      // [2][64]

    int rq = lane >> 2, cq = lane & 3;
    #pragma unroll
    for (int i = 0; i < 2; i++) {
        #pragma unroll
        for (int rh = 0; rh < 2; rh++) {
            float bv = -1e30f; int bc = 0x7fffffff;
            #pragma unroll
            for (int j = 0; j < 7; j++) {
                #pragma unroll
                for (int p = 0; p < 2; p++) {
                    int gc = half*112 + wc*56 + j*8 + cq*2 + p;
                    float v = acc[i][j][rh*2 + p];
                    if (gc < M_ && (v > bv || (v == bv && gc < bc))) { bv = v; bc = gc; }
                }
            }
            #pragma unroll
            for (int off = 1; off < 4; off <<= 1) {
                float ov = __shfl_xor_sync(0xffffffffu, bv, off);
                int   oc = __shfl_xor_sync(0xffffffffu, bc, off);
                if (ov > bv || (ov == bv && oc < bc)) { bv = ov; bc = oc; }
            }
            if (cq == 0) {
                int rl = wr*32 + i*16 + rh*8 + rq;      // CTA-local row 0..63
                sv[wc*64 + rl] = bv;
                sc[wc*64 + rl] = bc;
            }
        }
    }
    __syncthreads();

    if (tid < 64) {
        float v0 = sv[tid],      v1 = sv[64 + tid];
        int   c0 = sc[tid],      c1 = sc[64 + tid];
        float bv; int bc;
        if (v1 > v0) { bv = v1; bc = c1; } else { bv = v0; bc = c0; }
        int gr = mt*64 + tid;
        if (gr < Q_*M_) {
            int q = gr / M_, mq = gr % M_;
            int o = (((b*Q_ + q)*N_ + n)*2 + half)*M_ + mq;
            g_rowmax[o] = bv;
            g_rowarg[o] = bc;
        }
    }
}

// ---------------- per-(b,q) mutual-NN mask + predict + loss -----------------
__global__ void combine_kernel(const int* __restrict__ qy) {
    int bq = blockIdx.x;
    int tid = threadIdx.x;          // 256 threads

    __shared__ float rowm[N_][M_];
    __shared__ float bestv[M_];
    __shared__ int   bestj[M_];
    __shared__ int   maskf[M_];
    __shared__ float pred[N_];

    if (tid < M_) {
        float bv = -1e30f; int bj = 0;
        #pragma unroll
        for (int nn = 0; nn < N_; nn++) {
            int o0 = ((bq*N_ + nn)*2 + 0)*M_ + tid;
            int o1 = ((bq*N_ + nn)*2 + 1)*M_ + tid;
            float m0 = g_rowmax[o0]; int a0 = g_rowarg[o0];
            float m1 = g_rowmax[o1]; int a1 = g_rowarg[o1];
            float rv; int ra;
            if (m1 > m0) { rv = m1; ra = a1; } else { rv = m0; ra = a0; }
            rowm[nn][tid] = rv;
            if (rv > bv) { bv = rv; bj = nn*M_ + ra; }
        }
        bestv[tid] = bv; bestj[tid] = bj;
    }
    __syncthreads();

    if (tid < M_) {
        float v = bestv[tid]; int j = bestj[tid];
        int ok = (v + 1.0f) > 0.0f;
        for (int t = 0; t < M_; t++) {
            if (t == tid) continue;
            if (bestj[t] == j) {
                float vt = bestv[t];
                if (vt > v || (vt == v && t < tid)) ok = 0;
            }
        }
        maskf[tid] = ok;
    }
    __syncthreads();

    if (tid < N_) {
        float s = 0.f;
        for (int m = 0; m < M_; m++)
            if (maskf[m]) s += rowm[tid][m];
        pred[tid] = 2.0f * s;       // TEMPERATURE
    }
    __syncthreads();

    if (tid == 0) {
        float mx = pred[0];
        #pragma unroll
        for (int nn = 1; nn < N_; nn++) mx = fmaxf(mx, pred[nn]);
        float se = 0.f;
        #pragma unroll
        for (int nn = 0; nn < N_; nn++) se += expf(pred[nn] - mx);
        float lse = mx + logf(se);
        int y = qy[bq];
        g_loss[bq] = lse - pred[y];
    }
}

__global__ void final_kernel(float* __restrict__ out) {
    __shared__ float part[32];
    int lane = threadIdx.x;
    float s = 0.f;
    for (int i = lane; i < BQ_; i += 32) s += g_loss[i];
    part[lane] = s;
    __syncwarp();
    if (lane == 0) {
        float t = 0.f;
        #pragma unroll
        for (int w = 0; w < 32; w++) t += part[w];
        out[0] = t / (float)BQ_;
    }
}

extern "C" void kernel_launch(void* const* d_in, const int* in_sizes, int n_in,
                              void* d_out, int out_size) {
    const float* sup = (const float*)d_in[0];
    // d_in[1] = support_y : unused by the reference computation
    const float* qf  = (const float*)d_in[2];
    const int*   qy  = (const int*)d_in[3];

    cudaFuncSetAttribute(gemm_hmma, cudaFuncAttributeMaxDynamicSharedMemorySize, SMEM_BYTES);

    part_sumsq<<<dim3(20, NE_), 256>>>(sup, qf);      // launch 0
    rinv_k    <<<NE_, 224>>>();                       // launch 1
    tr_all    <<<dim3(20, NE_), 256>>>(sup, qf);      // launch 2

    dim3 grid(N_*2, MT_, B_);   // nh fastest -> A-tile L2 reuse
    gemm_hmma<<<grid, TPB, SMEM_BYTES>>>();           // launch 3 (ncu slot)

    combine_kernel<<<BQ_, 256>>>(qy);
    final_kernel  <<<1, 32>>>((float*)d_out);
}

// round 15
// speedup vs baseline: 1.1688x; 1.1492x over previous
#include <cuda_runtime.h>
#include <cuda_fp16.h>
#include <math.h>
#include <stdint.h>

#define B_   4
#define Q_   75
#define C_   640
#define M_   196
#define N_   5
#define KS_  5
#define BQ_  (B_*Q_)        // 300
#define NE_  (B_*N_ + BQ_)  // 320 entities
#define MT_  230            // M tiles of 64 per batch (230*64 = 14720)
#define RPB  14720          // padded query rows per batch
#define NPAD 224            // padded ms per class
#define KC   32             // K chunk (fp16)
#define KT_  (C_/KC)        // 20
#define TPB  128            // 4 warps per CTA

// rigorous |S - S_hi| bound for fp16 hi-only on unit vectors: 2u+eps ~ 1.0e-3.
// threshold = 2*delta with slack.
#define DELTA2 0.0025f

// smem stage layout (bytes), row stride 80B => conflict-free ldmatrix (hi only)
#define ROWB   80
#define AHI_O  0
#define BHI_O  5120
#define STAGEB 14080
#define SMEM_BYTES (2*STAGEB)   // 28160 per CTA

// ---------------- scratch (static device globals; zero-initialized) --------
__device__ __half g_qn_hi[(size_t)B_*RPB*C_];   // pad rows stay 0
__device__ __half g_qn_lo[(size_t)B_*RPB*C_];
__device__ __half g_sn_hi[B_*N_*NPAD*C_];       // pad rows 196..223 stay 0
__device__ __half g_sn_lo[B_*N_*NPAD*C_];
__device__ float g_part[NE_*20*M_];
__device__ float g_rinv[NE_*M_];
__device__ float g_hmax[BQ_*N_*2*M_];           // per (row, half): approx max
__device__ int   g_ccnt[BQ_*N_*2*M_];           // candidate count
__device__ uint2 g_cand[BQ_*N_*2*M_];           // up to 8 candidate cols (u8)
__device__ float g_rowmax[BQ_*N_*M_];           // exact rescored max
__device__ int   g_rowarg[BQ_*N_*M_];
__device__ float g_loss[BQ_];

// ---------------- PTX helpers ----------------------------------------------
__device__ __forceinline__ uint32_t s2u(const void* p) {
    uint32_t a;
    asm("{ .reg .u64 t; cvta.to.shared.u64 t, %1; cvt.u32.u64 %0, t; }"
        : "=r"(a) : "l"(p));
    return a;
}
__device__ __forceinline__ void cp16(uint32_t dst, const void* src) {
    asm volatile("cp.async.cg.shared.global [%0], [%1], 16;" :: "r"(dst), "l"(src));
}
__device__ __forceinline__ void ldsm4(uint32_t* r, uint32_t a) {
    asm volatile("ldmatrix.sync.aligned.m8n8.x4.shared.b16 {%0,%1,%2,%3}, [%4];"
                 : "=r"(r[0]), "=r"(r[1]), "=r"(r[2]), "=r"(r[3]) : "r"(a));
}
__device__ __forceinline__ void mma16816f(float* c, const uint32_t* a, const uint32_t* b) {
    asm volatile("mma.sync.aligned.m16n8k16.row.col.f32.f16.f16.f32 "
                 "{%0,%1,%2,%3}, {%4,%5,%6,%7}, {%8,%9}, {%0,%1,%2,%3};"
                 : "+f"(c[0]), "+f"(c[1]), "+f"(c[2]), "+f"(c[3])
                 : "r"(a[0]), "r"(a[1]), "r"(a[2]), "r"(a[3]), "r"(b[0]), "r"(b[1]));
}

// ---------------- P0: per-(entity, ctile) partial sumsq ---------------------
__global__ void __launch_bounds__(256)
part_sumsq(const float* __restrict__ sup, const float* __restrict__ qf) {
    int tc = blockIdx.x;
    int e  = blockIdx.y;
    int tid = threadIdx.x;
    __shared__ float tile[32][201];

    if (e < B_*N_) {
        const float* base = sup + (size_t)e * KS_ * C_ * M_;
        for (int idx = tid; idx < 32*M_; idx += 256) {
            int cc = idx / M_, m = idx - cc*M_;
            float v = 0.f;
            #pragma unroll
            for (int k = 0; k < KS_; k++)
                v += base[(size_t)k*C_*M_ + (size_t)(tc*32 + cc)*M_ + m];
            tile[cc][m] = v * 0.2f;
        }
    } else {
        const float* in = qf + (size_t)(e - B_*N_) * C_ * M_;
        for (int idx = tid; idx < 32*M_; idx += 256) {
            int cc = idx / M_, m = idx - cc*M_;
            tile[cc][m] = in[(size_t)(tc*32 + cc)*M_ + m];
        }
    }
    __syncthreads();
    if (tid < M_) {
        float s = 0.f;
        #pragma unroll
        for (int cc = 0; cc < 32; cc++) { float v = tile[cc][tid]; s += v*v; }
        g_part[(e*20 + tc)*M_ + tid] = s;
    }
}

// ---------------- P1: fold 20 partials -> rinv ------------------------------
__global__ void rinv_k() {
    int e = blockIdx.x;
    int m = threadIdx.x;
    if (m < M_) {
        float s = 0.f;
        #pragma unroll
        for (int tc = 0; tc < 20; tc++) s += g_part[(e*20 + tc)*M_ + m];
        g_rinv[e*M_ + m] = 1.0f / fmaxf(sqrtf(s), 1e-8f);
    }
}

// ---------------- TR: transpose + scale + split to fp16 hi/lo ---------------
__global__ void __launch_bounds__(256)
tr_all(const float* __restrict__ sup, const float* __restrict__ qf) {
    int tc = blockIdx.x;
    int e  = blockIdx.y;
    int tid = threadIdx.x;
    __shared__ float tile[32][201];

    if (e < B_*N_) {
        int bn = e;
        const float* base = sup + (size_t)bn * KS_ * C_ * M_;
        for (int idx = tid; idx < 32*M_; idx += 256) {
            int cc = idx / M_, m = idx - cc*M_;
            float v = 0.f;
            #pragma unroll
            for (int k = 0; k < KS_; k++)
                v += base[(size_t)k*C_*M_ + (size_t)(tc*32 + cc)*M_ + m];
            tile[cc][m] = v * 0.2f;
        }
        __syncthreads();
        size_t ob = (size_t)bn * NPAD * C_;
        const float* rv = g_rinv + e*M_;
        for (int idx = tid; idx < M_*32; idx += 256) {
            int m = idx >> 5, cc = idx & 31;
            float v = tile[cc][m] * rv[m];
            __half h = __float2half_rn(v);
            size_t o = ob + (size_t)m*C_ + tc*32 + cc;
            g_sn_hi[o] = h;
            g_sn_lo[o] = __float2half_rn(v - __half2float(h));
        }
    } else {
        int bq = e - B_*N_;
        int b = bq / Q_, q = bq % Q_;
        const float* in = qf + (size_t)bq * C_ * M_;
        for (int idx = tid; idx < 32*M_; idx += 256) {
            int cc = idx / M_, m = idx - cc*M_;
            tile[cc][m] = in[(size_t)(tc*32 + cc)*M_ + m];
        }
        __syncthreads();
        size_t rowbase = (size_t)b * RPB + (size_t)q * M_;
        const float* rv = g_rinv + e*M_;
        for (int idx = tid; idx < M_*32; idx += 256) {
            int m = idx >> 5, cc = idx & 31;
            float v = tile[cc][m] * rv[m];
            __half h = __float2half_rn(v);
            size_t o = (rowbase + m)*C_ + tc*32 + cc;
            g_qn_hi[o] = h;
            g_qn_lo[o] = __float2half_rn(v - __half2float(h));
        }
    }
}

// ---------------- fp16 hi-only HMMA GEMM + candidate epilogue ---------------
// 128-thr CTA, tile 64(mq) x 112(ms), warps 2x2 (32x56 each), 1 MMA term.
// Epilogue: per (row, half) approx max + candidate cols within DELTA2.
__global__ void __launch_bounds__(TPB, 4)
gemm_hi() {
    int nh = blockIdx.x;             // n*2 + half
    int n = nh >> 1, half = nh & 1;
    int mt = blockIdx.y, b = blockIdx.z;

    extern __shared__ char dynsm[];
    uint32_t sbase = s2u(dynsm);

    int tid = threadIdx.x, lane = tid & 31, wid = tid >> 5;
    int wr = wid >> 1, wc = wid & 1;

    const size_t arbase = (size_t)b * RPB + (size_t)mt * 64;
    const size_t brbase = (size_t)(b*N_ + n) * NPAD + (size_t)half * 112;

    // hoisted cp.async addressing (A: 2 slots/thr, B: 3 + cond 4th)
    int rA0 = tid >> 2,          cA0 = tid & 3;
    int itA1 = tid + 128;
    int rA1 = itA1 >> 2,         cA1 = itA1 & 3;
    const size_t gA0 = (arbase + rA0) * C_ + cA0*8;
    const size_t gA1 = (arbase + rA1) * C_ + cA1*8;
    const uint32_t dA0 = rA0*ROWB + cA0*16;
    const uint32_t dA1 = rA1*ROWB + cA1*16;
    int rB0 = tid >> 2,          cB0 = tid & 3;
    int itB1 = tid + 128;
    int rB1 = itB1 >> 2,         cB1 = itB1 & 3;
    int itB2 = tid + 256;
    int rB2 = itB2 >> 2,         cB2 = itB2 & 3;
    int itB3 = tid + 384;
    int rB3 = itB3 >> 2,         cB3 = itB3 & 3;
    const size_t gB0 = (brbase + rB0) * C_ + cB0*8;
    const size_t gB1 = (brbase + rB1) * C_ + cB1*8;
    const size_t gB2 = (brbase + rB2) * C_ + cB2*8;
    const size_t gB3 = (brbase + rB3) * C_ + cB3*8;
    const uint32_t dB0 = rB0*ROWB + cB0*16;
    const uint32_t dB1 = rB1*ROWB + cB1*16;
    const uint32_t dB2 = rB2*ROWB + cB2*16;
    const uint32_t dB3 = rB3*ROWB + cB3*16;
    const bool hasB3 = (tid < 64);

    auto issue = [&](int stage, int kt) {
        uint32_t so = sbase + stage * STAGEB;
        int ko = kt * KC;
        cp16(so + AHI_O + dA0, g_qn_hi + gA0 + ko);
        cp16(so + AHI_O + dA1, g_qn_hi + gA1 + ko);
        cp16(so + BHI_O + dB0, g_sn_hi + gB0 + ko);
        cp16(so + BHI_O + dB1, g_sn_hi + gB1 + ko);
        cp16(so + BHI_O + dB2, g_sn_hi + gB2 + ko);
        if (hasB3) cp16(so + BHI_O + dB3, g_sn_hi + gB3 + ko);
        asm volatile("cp.async.commit_group;" ::: "memory");
    };

    uint32_t aoff[2][2];
    {
        int arow = (lane & 7) + ((lane >> 3) & 1) * 8;
        int acolb = ((lane >> 4) & 1) * 16;
        #pragma unroll
        for (int i = 0; i < 2; i++)
            #pragma unroll
            for (int ks = 0; ks < 2; ks++)
                aoff[i][ks] = (uint32_t)((wr*32 + i*16 + arow)*ROWB + ks*32 + acolb);
    }
    const uint32_t boff0 = (uint32_t)((wc*56 + (lane & 7))*ROWB
                          + ((lane >> 4) & 1)*32 + ((lane >> 3) & 1)*16);

    float acc[2][7][4];
    #pragma unroll
    for (int i = 0; i < 2; i++)
        #pragma unroll
        for (int j = 0; j < 7; j++)
            #pragma unroll
            for (int p = 0; p < 4; p++) acc[i][j][p] = 0.f;

    issue(0, 0);

    #pragma unroll 1
    for (int kt = 0; kt < KT_; kt++) {
        if (kt + 1 < KT_) {
            issue((kt + 1) & 1, kt + 1);
            asm volatile("cp.async.wait_group 1;" ::: "memory");
        } else {
            asm volatile("cp.async.wait_group 0;" ::: "memory");
        }
        __syncthreads();

        uint32_t so = sbase + (kt & 1) * STAGEB;

        uint32_t Ahi[2][2][4];
        #pragma unroll
        for (int i = 0; i < 2; i++)
            #pragma unroll
            for (int ks = 0; ks < 2; ks++)
                ldsm4(Ahi[i][ks], so + AHI_O + aoff[i][ks]);

        uint32_t B4[2][4];                        // double buffer [buf][ks*2+kh]
        ldsm4(B4[0], so + BHI_O + boff0);

        #pragma unroll
        for (int j = 0; j < 7; j++) {
            int cur = j & 1;
            if (j < 6)
                ldsm4(B4[cur ^ 1], so + BHI_O + boff0 + (j+1)*(8*ROWB));
            #pragma unroll
            for (int ks = 0; ks < 2; ks++)
                #pragma unroll
                for (int i = 0; i < 2; i++)
                    mma16816f(acc[i][j], Ahi[i][ks], &B4[cur][ks*2]);
        }
        __syncthreads();
    }

    // ---- epilogue: approx max + candidate collection per (row, half) ----
    float*   sv   = (float*)dynsm;                 // [2][64]
    float*   mv   = (float*)(dynsm + 512);         // [64]
    int*     scnt = (int*)(dynsm + 768);           // [64]
    uint8_t* slst = (uint8_t*)(dynsm + 1024);      // [64][8]

    int rq = lane >> 2, cq = lane & 3;
    #pragma unroll
    for (int i = 0; i < 2; i++) {
        #pragma unroll
        for (int rh = 0; rh < 2; rh++) {
            float bv = -1e30f;
            #pragma unroll
            for (int j = 0; j < 7; j++)
                #pragma unroll
                for (int p = 0; p < 2; p++) {
                    int gc = half*112 + wc*56 + j*8 + cq*2 + p;
                    float v = acc[i][j][rh*2 + p];
                    if (gc < M_ && v > bv) bv = v;
                }
            #pragma unroll
            for (int off = 1; off < 4; off <<= 1) {
                float ov = __shfl_xor_sync(0xffffffffu, bv, off);
                if (ov > bv) bv = ov;
            }
            if (cq == 0) {
                int rl = wr*32 + i*16 + rh*8 + rq;
                sv[wc*64 + rl] = bv;
            }
        }
    }
    __syncthreads();
    if (tid < 64) {
        mv[tid] = fmaxf(sv[tid], sv[64 + tid]);
        scnt[tid] = 0;
    }
    __syncthreads();
    // candidate scan
    #pragma unroll
    for (int i = 0; i < 2; i++) {
        #pragma unroll
        for (int rh = 0; rh < 2; rh++) {
            int rl = wr*32 + i*16 + rh*8 + rq;
            float t = mv[rl] - DELTA2;
            #pragma unroll
            for (int j = 0; j < 7; j++)
                #pragma unroll
                for (int p = 0; p < 2; p++) {
                    int gc = half*112 + wc*56 + j*8 + cq*2 + p;
                    float v = acc[i][j][rh*2 + p];
                    if (gc < M_ && v > t) {
                        int pos = atomicAdd(&scnt[rl], 1);
                        if (pos < 8) slst[rl*8 + pos] = (uint8_t)gc;
                    }
                }
        }
    }
    __syncthreads();
    if (tid < 64) {
        int gr = mt*64 + tid;
        if (gr < Q_*M_) {
            int q = gr / M_, mq = gr % M_;
            int o = (((b*Q_ + q)*N_ + n)*2 + half)*M_ + mq;
            g_hmax[o] = mv[tid];
            g_ccnt[o] = scnt[tid];
            g_cand[o] = *(uint2*)(slst + tid*8);
        }
    }
}

// ---------------- rescore: exact fp32 dots for candidates -------------------
// Block per (mq, bq); 5 warps = 5 classes. q row reconstructed once in smem.
__global__ void __launch_bounds__(160)
rescore() {
    int mq = blockIdx.x, bq = blockIdx.y;
    int b = bq / Q_, q = bq % Q_;
    __shared__ float qrow[C_];
    int tid = threadIdx.x;

    size_t qb = ((size_t)b * RPB + (size_t)q * M_ + mq) * C_;
    for (int c = tid; c < C_; c += 160)
        qrow[c] = __half2float(g_qn_hi[qb + c]) + __half2float(g_qn_lo[qb + c]);
    __syncthreads();

    int w = tid >> 5, lane = tid & 31;
    if (w >= N_) return;
    int n = w;

    int o0 = ((bq*N_ + n)*2 + 0)*M_ + mq;
    int o1 = o0 + M_;
    float m0 = g_hmax[o0], m1 = g_hmax[o1];
    float mg = fmaxf(m0, m1);

    float bv = -1e30f; int bc = 0x7fffffff;
    const size_t snb = (size_t)(b*N_ + n) * NPAD * C_;

    #pragma unroll
    for (int half = 0; half < 2; half++) {
        float mh = half ? m1 : m0;
        if (mh < mg - DELTA2) continue;          // half can't contain true max
        int o = half ? o1 : o0;
        int cnt = g_ccnt[o];

        auto eval = [&](int gc) {
            const __half* sh = g_sn_hi + snb + (size_t)gc * C_;
            const __half* sl = g_sn_lo + snb + (size_t)gc * C_;
            float s = 0.f;
            for (int c = lane; c < C_; c += 32)
                s += qrow[c] * (__half2float(sh[c]) + __half2float(sl[c]));
            #pragma unroll
            for (int off = 16; off > 0; off >>= 1)
                s += __shfl_xor_sync(0xffffffffu, s, off);
            if (s > bv || (s == bv && gc < bc)) { bv = s; bc = gc; }
        };

        if (cnt <= 8) {
            uint2 pk = g_cand[o];
            for (int k = 0; k < cnt; k++) {
                uint32_t w32 = (k < 4) ? pk.x : pk.y;
                int gc = (w32 >> ((k & 3) * 8)) & 0xFF;
                eval(gc);
            }
        } else {                                   // overflow: full half scan
            int lo = half*112;
            int hi = (lo + 112 < M_) ? lo + 112 : M_;
            for (int gc = lo; gc < hi; gc++) eval(gc);
        }
    }

    if (lane == 0) {
        int o = (bq*N_ + n)*M_ + mq;
        g_rowmax[o] = bv;
        g_rowarg[o] = bc;
    }
}

// ---------------- per-(b,q) mutual-NN mask + predict + loss -----------------
__global__ void combine_kernel(const int* __restrict__ qy) {
    int bq = blockIdx.x;
    int tid = threadIdx.x;          // 256 threads

    __shared__ float rowm[N_][M_];
    __shared__ float bestv[M_];
    __shared__ int   bestj[M_];
    __shared__ int   maskf[M_];
    __shared__ float pred[N_];

    if (tid < M_) {
        float bv = -1e30f; int bj = 0;
        #pragma unroll
        for (int nn = 0; nn < N_; nn++) {
            int o = (bq*N_ + nn)*M_ + tid;
            float rv = g_rowmax[o];
            int   ra = g_rowarg[o];
            rowm[nn][tid] = rv;
            if (rv > bv) { bv = rv; bj = nn*M_ + ra; }   // ascending n
        }
        bestv[tid] = bv; bestj[tid] = bj;
    }
    __syncthreads();

    if (tid < M_) {
        float v = bestv[tid]; int j = bestj[tid];
        int ok = (v + 1.0f) > 0.0f;
        for (int t = 0; t < M_; t++) {
            if (t == tid) continue;
            if (bestj[t] == j) {
                float vt = bestv[t];
                if (vt > v || (vt == v && t < tid)) ok = 0;
            }
        }
        maskf[tid] = ok;
    }
    __syncthreads();

    if (tid < N_) {
        float s = 0.f;
        for (int m = 0; m < M_; m++)
            if (maskf[m]) s += rowm[tid][m];
        pred[tid] = 2.0f * s;       // TEMPERATURE
    }
    __syncthreads();

    if (tid == 0) {
        float mx = pred[0];
        #pragma unroll
        for (int nn = 1; nn < N_; nn++) mx = fmaxf(mx, pred[nn]);
        float se = 0.f;
        #pragma unroll
        for (int nn = 0; nn < N_; nn++) se += expf(pred[nn] - mx);
        float lse = mx + logf(se);
        int y = qy[bq];
        g_loss[bq] = lse - pred[y];
    }
}

__global__ void final_kernel(float* __restrict__ out) {
    __shared__ float part[32];
    int lane = threadIdx.x;
    float s = 0.f;
    for (int i = lane; i < BQ_; i += 32) s += g_loss[i];
    part[lane] = s;
    __syncwarp();
    if (lane == 0) {
        float t = 0.f;
        #pragma unroll
        for (int w = 0; w < 32; w++) t += part[w];
        out[0] = t / (float)BQ_;
    }
}

extern "C" void kernel_launch(void* const* d_in, const int* in_sizes, int n_in,
                              void* d_out, int out_size) {
    const float* sup = (const float*)d_in[0];
    // d_in[1] = support_y : unused by the reference computation
    const float* qf  = (const float*)d_in[2];
    const int*   qy  = (const int*)d_in[3];

    cudaFuncSetAttribute(gemm_hi, cudaFuncAttributeMaxDynamicSharedMemorySize, SMEM_BYTES);

    part_sumsq<<<dim3(20, NE_), 256>>>(sup, qf);      // launch 0
    rinv_k    <<<NE_, 224>>>();                       // launch 1
    tr_all    <<<dim3(20, NE_), 256>>>(sup, qf);      // launch 2

    dim3 grid(N_*2, MT_, B_);
    gemm_hi<<<grid, TPB, SMEM_BYTES>>>();             // launch 3 (ncu slot)

    rescore<<<dim3(M_, BQ_), 160>>>();                // launch 4
    combine_kernel<<<BQ_, 256>>>(qy);                 // launch 5
    final_kernel  <<<1, 32>>>((float*)d_out);         // launch 6
}

// round 16
// speedup vs baseline: 1.2517x; 1.0709x over previous
#include <cuda_runtime.h>
#include <cuda_fp16.h>
#include <math.h>
#include <stdint.h>

#define B_   4
#define Q_   75
#define C_   640
#define M_   196
#define N_   5
#define KS_  5
#define BQ_  (B_*Q_)        // 300
#define NE_  (B_*N_ + BQ_)  // 320 entities
#define MT_  230            // M tiles of 64 per batch (230*64 = 14720)
#define RPB  14720          // padded query rows per batch
#define NPAD 224            // padded ms per class
#define KC   32             // K chunk (fp16)
#define KT_  (C_/KC)        // 20
#define TPB  128            // 4 warps per CTA

// rigorous |S - S_hi| bound for fp16 hi-only on unit vectors: 2u+eps ~ 1.0e-3.
#define DELTA2 0.0025f

// smem stage layout (bytes), row stride 80B => conflict-free ldmatrix (hi only)
#define ROWB   80
#define AHI_O  0
#define BHI_O  5120
#define STAGEB 14080
#define SMEM_BYTES (2*STAGEB)   // 28160 per CTA

// ---------------- scratch (static device globals; zero-initialized) --------
__device__ __half g_qn_hi[(size_t)B_*RPB*C_];   // pad rows stay 0
__device__ __half g_qn_lo[(size_t)B_*RPB*C_];
__device__ __half g_sn_hi[B_*N_*NPAD*C_];       // pad rows 196..223 stay 0
__device__ float  g_s32 [B_*N_*NPAD*C_];        // fp32 support (rescore path)
__device__ float g_part[NE_*20*M_];
__device__ float g_rinv[NE_*M_];
__device__ float g_hmax[BQ_*N_*2*M_];           // per (row, half): approx max
__device__ int   g_ccnt[BQ_*N_*2*M_];           // candidate count
__device__ uint2 g_cand[BQ_*N_*2*M_];           // up to 8 candidate cols (u8)
__device__ float g_rowmax[BQ_*N_*M_];           // exact rescored max
__device__ int   g_rowarg[BQ_*N_*M_];
__device__ float g_loss[BQ_];

// ---------------- PTX helpers ----------------------------------------------
__device__ __forceinline__ uint32_t s2u(const void* p) {
    uint32_t a;
    asm("{ .reg .u64 t; cvta.to.shared.u64 t, %1; cvt.u32.u64 %0, t; }"
        : "=r"(a) : "l"(p));
    return a;
}
__device__ __forceinline__ void cp16(uint32_t dst, const void* src) {
    asm volatile("cp.async.cg.shared.global [%0], [%1], 16;" :: "r"(dst), "l"(src));
}
__device__ __forceinline__ void ldsm4(uint32_t* r, uint32_t a) {
    asm volatile("ldmatrix.sync.aligned.m8n8.x4.shared.b16 {%0,%1,%2,%3}, [%4];"
                 : "=r"(r[0]), "=r"(r[1]), "=r"(r[2]), "=r"(r[3]) : "r"(a));
}
__device__ __forceinline__ void mma16816f(float* c, const uint32_t* a, const uint32_t* b) {
    asm volatile("mma.sync.aligned.m16n8k16.row.col.f32.f16.f16.f32 "
                 "{%0,%1,%2,%3}, {%4,%5,%6,%7}, {%8,%9}, {%0,%1,%2,%3};"
                 : "+f"(c[0]), "+f"(c[1]), "+f"(c[2]), "+f"(c[3])
                 : "r"(a[0]), "r"(a[1]), "r"(a[2]), "r"(a[3]), "r"(b[0]), "r"(b[1]));
}

// ---------------- P0: per-(entity, ctile) partial sumsq ---------------------
__global__ void __launch_bounds__(256)
part_sumsq(const float* __restrict__ sup, const float* __restrict__ qf) {
    int tc = blockIdx.x;
    int e  = blockIdx.y;
    int tid = threadIdx.x;
    __shared__ float tile[32][201];

    if (e < B_*N_) {
        const float* base = sup + (size_t)e * KS_ * C_ * M_;
        for (int idx = tid; idx < 32*M_; idx += 256) {
            int cc = idx / M_, m = idx - cc*M_;
            float v = 0.f;
            #pragma unroll
            for (int k = 0; k < KS_; k++)
                v += base[(size_t)k*C_*M_ + (size_t)(tc*32 + cc)*M_ + m];
            tile[cc][m] = v * 0.2f;
        }
    } else {
        const float* in = qf + (size_t)(e - B_*N_) * C_ * M_;
        for (int idx = tid; idx < 32*M_; idx += 256) {
            int cc = idx / M_, m = idx - cc*M_;
            tile[cc][m] = in[(size_t)(tc*32 + cc)*M_ + m];
        }
    }
    __syncthreads();
    if (tid < M_) {
        float s = 0.f;
        #pragma unroll
        for (int cc = 0; cc < 32; cc++) { float v = tile[cc][tid]; s += v*v; }
        g_part[(e*20 + tc)*M_ + tid] = s;
    }
}

// ---------------- P1: fold 20 partials -> rinv ------------------------------
__global__ void rinv_k() {
    int e = blockIdx.x;
    int m = threadIdx.x;
    if (m < M_) {
        float s = 0.f;
        #pragma unroll
        for (int tc = 0; tc < 20; tc++) s += g_part[(e*20 + tc)*M_ + m];
        g_rinv[e*M_ + m] = 1.0f / fmaxf(sqrtf(s), 1e-8f);
    }
}

// ---------------- TR: transpose + scale + split ------------------------------
// support: fp16 hi (gemm) + fp32 (rescore). query: fp16 hi + fp16 lo.
__global__ void __launch_bounds__(256)
tr_all(const float* __restrict__ sup, const float* __restrict__ qf) {
    int tc = blockIdx.x;
    int e  = blockIdx.y;
    int tid = threadIdx.x;
    __shared__ float tile[32][201];

    if (e < B_*N_) {
        int bn = e;
        const float* base = sup + (size_t)bn * KS_ * C_ * M_;
        for (int idx = tid; idx < 32*M_; idx += 256) {
            int cc = idx / M_, m = idx - cc*M_;
            float v = 0.f;
            #pragma unroll
            for (int k = 0; k < KS_; k++)
                v += base[(size_t)k*C_*M_ + (size_t)(tc*32 + cc)*M_ + m];
            tile[cc][m] = v * 0.2f;
        }
        __syncthreads();
        size_t ob = (size_t)bn * NPAD * C_;
        const float* rv = g_rinv + e*M_;
        for (int idx = tid; idx < M_*32; idx += 256) {
            int m = idx >> 5, cc = idx & 31;
            float v = tile[cc][m] * rv[m];
            size_t o = ob + (size_t)m*C_ + tc*32 + cc;
            g_sn_hi[o] = __float2half_rn(v);
            g_s32[o] = v;
        }
    } else {
        int bq = e - B_*N_;
        int b = bq / Q_, q = bq % Q_;
        const float* in = qf + (size_t)bq * C_ * M_;
        for (int idx = tid; idx < 32*M_; idx += 256) {
            int cc = idx / M_, m = idx - cc*M_;
            tile[cc][m] = in[(size_t)(tc*32 + cc)*M_ + m];
        }
        __syncthreads();
        size_t rowbase = (size_t)b * RPB + (size_t)q * M_;
        const float* rv = g_rinv + e*M_;
        for (int idx = tid; idx < M_*32; idx += 256) {
            int m = idx >> 5, cc = idx & 31;
            float v = tile[cc][m] * rv[m];
            __half h = __float2half_rn(v);
            size_t o = (rowbase + m)*C_ + tc*32 + cc;
            g_qn_hi[o] = h;
            g_qn_lo[o] = __float2half_rn(v - __half2float(h));
        }
    }
}

// ---------------- fp16 hi-only HMMA GEMM + candidate epilogue ---------------
__global__ void __launch_bounds__(TPB, 4)
gemm_hi() {
    int nh = blockIdx.x;             // n*2 + half
    int n = nh >> 1, half = nh & 1;
    int mt = blockIdx.y, b = blockIdx.z;

    extern __shared__ char dynsm[];
    uint32_t sbase = s2u(dynsm);

    int tid = threadIdx.x, lane = tid & 31, wid = tid >> 5;
    int wr = wid >> 1, wc = wid & 1;

    const size_t arbase = (size_t)b * RPB + (size_t)mt * 64;
    const size_t brbase = (size_t)(b*N_ + n) * NPAD + (size_t)half * 112;

    int rA0 = tid >> 2,          cA0 = tid & 3;
    int itA1 = tid + 128;
    int rA1 = itA1 >> 2,         cA1 = itA1 & 3;
    const size_t gA0 = (arbase + rA0) * C_ + cA0*8;
    const size_t gA1 = (arbase + rA1) * C_ + cA1*8;
    const uint32_t dA0 = rA0*ROWB + cA0*16;
    const uint32_t dA1 = rA1*ROWB + cA1*16;
    int rB0 = tid >> 2,          cB0 = tid & 3;
    int itB1 = tid + 128;
    int rB1 = itB1 >> 2,         cB1 = itB1 & 3;
    int itB2 = tid + 256;
    int rB2 = itB2 >> 2,         cB2 = itB2 & 3;
    int itB3 = tid + 384;
    int rB3 = itB3 >> 2,         cB3 = itB3 & 3;
    const size_t gB0 = (brbase + rB0) * C_ + cB0*8;
    const size_t gB1 = (brbase + rB1) * C_ + cB1*8;
    const size_t gB2 = (brbase + rB2) * C_ + cB2*8;
    const size_t gB3 = (brbase + rB3) * C_ + cB3*8;
    const uint32_t dB0 = rB0*ROWB + cB0*16;
    const uint32_t dB1 = rB1*ROWB + cB1*16;
    const uint32_t dB2 = rB2*ROWB + cB2*16;
    const uint32_t dB3 = rB3*ROWB + cB3*16;
    const bool hasB3 = (tid < 64);

    auto issue = [&](int stage, int kt) {
        uint32_t so = sbase + stage * STAGEB;
        int ko = kt * KC;
        cp16(so + AHI_O + dA0, g_qn_hi + gA0 + ko);
        cp16(so + AHI_O + dA1, g_qn_hi + gA1 + ko);
        cp16(so + BHI_O + dB0, g_sn_hi + gB0 + ko);
        cp16(so + BHI_O + dB1, g_sn_hi + gB1 + ko);
        cp16(so + BHI_O + dB2, g_sn_hi + gB2 + ko);
        if (hasB3) cp16(so + BHI_O + dB3, g_sn_hi + gB3 + ko);
        asm volatile("cp.async.commit_group;" ::: "memory");
    };

    uint32_t aoff[2][2];
    {
        int arow = (lane & 7) + ((lane >> 3) & 1) * 8;
        int acolb = ((lane >> 4) & 1) * 16;
        #pragma unroll
        for (int i = 0; i < 2; i++)
            #pragma unroll
            for (int ks = 0; ks < 2; ks++)
                aoff[i][ks] = (uint32_t)((wr*32 + i*16 + arow)*ROWB + ks*32 + acolb);
    }
    const uint32_t boff0 = (uint32_t)((wc*56 + (lane & 7))*ROWB
                          + ((lane >> 4) & 1)*32 + ((lane >> 3) & 1)*16);

    float acc[2][7][4];
    #pragma unroll
    for (int i = 0; i < 2; i++)
        #pragma unroll
        for (int j = 0; j < 7; j++)
            #pragma unroll
            for (int p = 0; p < 4; p++) acc[i][j][p] = 0.f;

    issue(0, 0);

    #pragma unroll 1
    for (int kt = 0; kt < KT_; kt++) {
        if (kt + 1 < KT_) {
            issue((kt + 1) & 1, kt + 1);
            asm volatile("cp.async.wait_group 1;" ::: "memory");
        } else {
            asm volatile("cp.async.wait_group 0;" ::: "memory");
        }
        __syncthreads();

        uint32_t so = sbase + (kt & 1) * STAGEB;

        uint32_t Ahi[2][2][4];
        #pragma unroll
        for (int i = 0; i < 2; i++)
            #pragma unroll
            for (int ks = 0; ks < 2; ks++)
                ldsm4(Ahi[i][ks], so + AHI_O + aoff[i][ks]);

        uint32_t B4[2][4];
        ldsm4(B4[0], so + BHI_O + boff0);

        #pragma unroll
        for (int j = 0; j < 7; j++) {
            int cur = j & 1;
            if (j < 6)
                ldsm4(B4[cur ^ 1], so + BHI_O + boff0 + (j+1)*(8*ROWB));
            #pragma unroll
            for (int ks = 0; ks < 2; ks++)
                #pragma unroll
                for (int i = 0; i < 2; i++)
                    mma16816f(acc[i][j], Ahi[i][ks], &B4[cur][ks*2]);
        }
        __syncthreads();
    }

    // ---- epilogue: approx max + candidate collection per (row, half) ----
    float*   sv   = (float*)dynsm;                 // [2][64]
    float*   mv   = (float*)(dynsm + 512);         // [64]
    int*     scnt = (int*)(dynsm + 768);           // [64]
    uint8_t* slst = (uint8_t*)(dynsm + 1024);      // [64][8]

    int rq = lane >> 2, cq = lane & 3;
    #pragma unroll
    for (int i = 0; i < 2; i++) {
        #pragma unroll
        for (int rh = 0; rh < 2; rh++) {
            float bv = -1e30f;
            #pragma unroll
            for (int j = 0; j < 7; j++)
                #pragma unroll
                for (int p = 0; p < 2; p++) {
                    int gc = half*112 + wc*56 + j*8 + cq*2 + p;
                    float v = acc[i][j][rh*2 + p];
                    if (gc < M_ && v > bv) bv = v;
                }
            #pragma unroll
            for (int off = 1; off < 4; off <<= 1) {
                float ov = __shfl_xor_sync(0xffffffffu, bv, off);
                if (ov > bv) bv = ov;
            }
            if (cq == 0) {
                int rl = wr*32 + i*16 + rh*8 + rq;
                sv[wc*64 + rl] = bv;
            }
        }
    }
    __syncthreads();
    if (tid < 64) {
        mv[tid] = fmaxf(sv[tid], sv[64 + tid]);
        scnt[tid] = 0;
    }
    __syncthreads();
    #pragma unroll
    for (int i = 0; i < 2; i++) {
        #pragma unroll
        for (int rh = 0; rh < 2; rh++) {
            int rl = wr*32 + i*16 + rh*8 + rq;
            float t = mv[rl] - DELTA2;
            #pragma unroll
            for (int j = 0; j < 7; j++)
                #pragma unroll
                for (int p = 0; p < 2; p++) {
                    int gc = half*112 + wc*56 + j*8 + cq*2 + p;
                    float v = acc[i][j][rh*2 + p];
                    if (gc < M_ && v > t) {
                        int pos = atomicAdd(&scnt[rl], 1);
                        if (pos < 8) slst[rl*8 + pos] = (uint8_t)gc;
                    }
                }
        }
    }
    __syncthreads();
    if (tid < 64) {
        int gr = mt*64 + tid;
        if (gr < Q_*M_) {
            int q = gr / M_, mq = gr % M_;
            int o = (((b*Q_ + q)*N_ + n)*2 + half)*M_ + mq;
            g_hmax[o] = mv[tid];
            g_ccnt[o] = scnt[tid];
            g_cand[o] = *(uint2*)(slst + tid*8);
        }
    }
}

// ---------------- rescore: exact fp32 dots for candidates (float4 path) -----
__global__ void __launch_bounds__(160)
rescore() {
    int mq = blockIdx.x, bq = blockIdx.y;
    int b = bq / Q_, q = bq % Q_;
    __shared__ __align__(16) float qrow[C_];
    int tid = threadIdx.x;

    size_t qb = ((size_t)b * RPB + (size_t)q * M_ + mq) * C_;
    for (int c = tid; c < C_; c += 160)
        qrow[c] = __half2float(g_qn_hi[qb + c]) + __half2float(g_qn_lo[qb + c]);
    __syncthreads();

    int w = tid >> 5, lane = tid & 31;
    if (w >= N_) return;
    int n = w;

    int o0 = ((bq*N_ + n)*2 + 0)*M_ + mq;
    int o1 = o0 + M_;
    float m0 = g_hmax[o0], m1 = g_hmax[o1];
    float mg = fmaxf(m0, m1);

    float bv = -1e30f; int bc = 0x7fffffff;
    const size_t snb = (size_t)(b*N_ + n) * NPAD * C_;
    const float4* q4 = (const float4*)qrow;

    #pragma unroll
    for (int half = 0; half < 2; half++) {
        float mh = half ? m1 : m0;
        if (mh < mg - DELTA2) continue;
        int o = half ? o1 : o0;
        int cnt = g_ccnt[o];

        auto eval = [&](int gc) {
            const float4* s4 = (const float4*)(g_s32 + snb + (size_t)gc * C_);
            float s = 0.f;
            #pragma unroll
            for (int it = 0; it < 5; it++) {          // 640/(32*4) = 5
                float4 aa = q4[lane + it*32];
                float4 bb = s4[lane + it*32];
                s += aa.x*bb.x + aa.y*bb.y + aa.z*bb.z + aa.w*bb.w;
            }
            #pragma unroll
            for (int off = 16; off > 0; off >>= 1)
                s += __shfl_xor_sync(0xffffffffu, s, off);
            if (s > bv || (s == bv && gc < bc)) { bv = s; bc = gc; }
        };

        if (cnt <= 8) {
            uint2 pk = g_cand[o];
            for (int k = 0; k < cnt; k++) {
                uint32_t w32 = (k < 4) ? pk.x : pk.y;
                int gc = (w32 >> ((k & 3) * 8)) & 0xFF;
                eval(gc);
            }
        } else {                                   // overflow: full half scan
            int lo = half*112;
            int hi = (lo + 112 < M_) ? lo + 112 : M_;
            for (int gc = lo; gc < hi; gc++) eval(gc);
        }
    }

    if (lane == 0) {
        int o = (bq*N_ + n)*M_ + mq;
        g_rowmax[o] = bv;
        g_rowarg[o] = bc;
    }
}

// ---------------- per-(b,q) mutual-NN mask + predict + loss -----------------
__global__ void combine_kernel(const int* __restrict__ qy) {
    int bq = blockIdx.x;
    int tid = threadIdx.x;          // 256 threads

    __shared__ float rowm[N_][M_];
    __shared__ float bestv[M_];
    __shared__ int   bestj[M_];
    __shared__ int   maskf[M_];
    __shared__ float pred[N_];

    if (tid < M_) {
        float bv = -1e30f; int bj = 0;
        #pragma unroll
        for (int nn = 0; nn < N_; nn++) {
            int o = (bq*N_ + nn)*M_ + tid;
            float rv = g_rowmax[o];
            int   ra = g_rowarg[o];
            rowm[nn][tid] = rv;
            if (rv > bv) { bv = rv; bj = nn*M_ + ra; }   // ascending n
        }
        bestv[tid] = bv; bestj[tid] = bj;
    }
    __syncthreads();

    if (tid < M_) {
        float v = bestv[tid]; int j = bestj[tid];
        int ok = (v + 1.0f) > 0.0f;
        for (int t = 0; t < M_; t++) {
            if (t == tid) continue;
            if (bestj[t] == j) {
                float vt = bestv[t];
                if (vt > v || (vt == v && t < tid)) ok = 0;
            }
        }
        maskf[tid] = ok;
    }
    __syncthreads();

    if (tid < N_) {
        float s = 0.f;
        for (int m = 0; m < M_; m++)
            if (maskf[m]) s += rowm[tid][m];
        pred[tid] = 2.0f * s;       // TEMPERATURE
    }
    __syncthreads();

    if (tid == 0) {
        float mx = pred[0];
        #pragma unroll
        for (int nn = 1; nn < N_; nn++) mx = fmaxf(mx, pred[nn]);
        float se = 0.f;
        #pragma unroll
        for (int nn = 0; nn < N_; nn++) se += expf(pred[nn] - mx);
        float lse = mx + logf(se);
        int y = qy[bq];
        g_loss[bq] = lse - pred[y];
    }
}

__global__ void final_kernel(float* __restrict__ out) {
    __shared__ float part[32];
    int lane = threadIdx.x;
    float s = 0.f;
    for (int i = lane; i < BQ_; i += 32) s += g_loss[i];
    part[lane] = s;
    __syncwarp();
    if (lane == 0) {
        float t = 0.f;
        #pragma unroll
        for (int w = 0; w < 32; w++) t += part[w];
        out[0] = t / (float)BQ_;
    }
}

extern "C" void kernel_launch(void* const* d_in, const int* in_sizes, int n_in,
                              void* d_out, int out_size) {
    const float* sup = (const float*)d_in[0];
    // d_in[1] = support_y : unused by the reference computation
    const float* qf  = (const float*)d_in[2];
    const int*   qy  = (const int*)d_in[3];

    cudaFuncSetAttribute(gemm_hi, cudaFuncAttributeMaxDynamicSharedMemorySize, SMEM_BYTES);

    part_sumsq<<<dim3(20, NE_), 256>>>(sup, qf);      // launch 0
    rinv_k    <<<NE_, 224>>>();                       // launch 1
    tr_all    <<<dim3(20, NE_), 256>>>(sup, qf);      // launch 2

    dim3 grid(N_*2, MT_, B_);
    gemm_hi<<<grid, TPB, SMEM_BYTES>>>();             // launch 3 (ncu slot)

    rescore<<<dim3(M_, BQ_), 160>>>();                // launch 4
    combine_kernel<<<BQ_, 256>>>(qy);                 // launch 5
    final_kernel  <<<1, 32>>>((float*)d_out);         // launch 6
}

// round 17
// speedup vs baseline: 1.5278x; 1.2206x over previous
#include <cuda_runtime.h>
#include <cuda_fp16.h>
#include <math.h>
#include <stdint.h>

#define B_   4
#define Q_   75
#define C_   640
#define M_   196
#define N_   5
#define KS_  5
#define BQ_  (B_*Q_)        // 300
#define NE_  (B_*N_ + BQ_)  // 320 entities
#define MT_  230            // M tiles of 64 per batch (230*64 = 14720)
#define RPB  14720          // padded query rows per batch
#define NPAD 224            // padded ms per class
#define KC   32             // K chunk (fp16)
#define KT_  (C_/KC)        // 20
#define TPB  128            // 4 warps per CTA

// rigorous |S - S_hi| bound for fp16 hi-only on unit vectors: 2u+eps ~ 1.0e-3.
#define DELTA2 0.0025f

// smem stage layout (bytes), row stride 80B => conflict-free ldmatrix (hi only)
#define ROWB   80
#define AHI_O  0
#define BHI_O  5120
#define STAGEB 14080
#define SMEM_BYTES (2*STAGEB)   // 28160 per CTA

// ---------------- scratch (static device globals; zero-initialized) --------
__device__ __half g_qn_hi[(size_t)B_*RPB*C_];   // pad rows stay 0
__device__ __half g_qn_lo[(size_t)B_*RPB*C_];
__device__ __half g_sn_hi[B_*N_*NPAD*C_];       // pad rows 196..223 stay 0
__device__ float  g_s32 [B_*N_*NPAD*C_];        // fp32 support (rescore path)
__device__ float g_part[NE_*20*M_];
__device__ float g_rinv[NE_*M_];
__device__ float g_hmax[BQ_*N_*2*M_];           // per (row, half): approx max
__device__ int   g_ccnt[BQ_*N_*2*M_];           // candidate count
__device__ uint2 g_cand[BQ_*N_*2*M_];           // up to 8 candidate cols (u8)
__device__ float g_rowmax[BQ_*N_*M_];           // exact rescored max
__device__ int   g_rowarg[BQ_*N_*M_];
__device__ float g_loss[BQ_];

// ---------------- PTX helpers ----------------------------------------------
__device__ __forceinline__ uint32_t s2u(const void* p) {
    uint32_t a;
    asm("{ .reg .u64 t; cvta.to.shared.u64 t, %1; cvt.u32.u64 %0, t; }"
        : "=r"(a) : "l"(p));
    return a;
}
__device__ __forceinline__ void cp16(uint32_t dst, const void* src) {
    asm volatile("cp.async.cg.shared.global [%0], [%1], 16;" :: "r"(dst), "l"(src));
}
__device__ __forceinline__ void ldsm4(uint32_t* r, uint32_t a) {
    asm volatile("ldmatrix.sync.aligned.m8n8.x4.shared.b16 {%0,%1,%2,%3}, [%4];"
                 : "=r"(r[0]), "=r"(r[1]), "=r"(r[2]), "=r"(r[3]) : "r"(a));
}
__device__ __forceinline__ void mma16816f(float* c, const uint32_t* a, const uint32_t* b) {
    asm volatile("mma.sync.aligned.m16n8k16.row.col.f32.f16.f16.f32 "
                 "{%0,%1,%2,%3}, {%4,%5,%6,%7}, {%8,%9}, {%0,%1,%2,%3};"
                 : "+f"(c[0]), "+f"(c[1]), "+f"(c[2]), "+f"(c[3])
                 : "r"(a[0]), "r"(a[1]), "r"(a[2]), "r"(a[3]), "r"(b[0]), "r"(b[1]));
}

// ---------------- P0: per-(entity, ctile) partial sumsq ---------------------
__global__ void __launch_bounds__(256)
part_sumsq(const float* __restrict__ sup, const float* __restrict__ qf) {
    int tc = blockIdx.x;
    int e  = blockIdx.y;
    int tid = threadIdx.x;
    __shared__ float tile[32][201];

    if (e < B_*N_) {
        const float* base = sup + (size_t)e * KS_ * C_ * M_;
        for (int idx = tid; idx < 32*M_; idx += 256) {
            int cc = idx / M_, m = idx - cc*M_;
            float v = 0.f;
            #pragma unroll
            for (int k = 0; k < KS_; k++)
                v += base[(size_t)k*C_*M_ + (size_t)(tc*32 + cc)*M_ + m];
            tile[cc][m] = v * 0.2f;
        }
    } else {
        const float* in = qf + (size_t)(e - B_*N_) * C_ * M_;
        for (int idx = tid; idx < 32*M_; idx += 256) {
            int cc = idx / M_, m = idx - cc*M_;
            tile[cc][m] = in[(size_t)(tc*32 + cc)*M_ + m];
        }
    }
    __syncthreads();
    if (tid < M_) {
        float s = 0.f;
        #pragma unroll
        for (int cc = 0; cc < 32; cc++) { float v = tile[cc][tid]; s += v*v; }
        g_part[(e*20 + tc)*M_ + tid] = s;
    }
}

// ---------------- P1: fold 20 partials -> rinv ------------------------------
__global__ void rinv_k() {
    int e = blockIdx.x;
    int m = threadIdx.x;
    if (m < M_) {
        float s = 0.f;
        #pragma unroll
        for (int tc = 0; tc < 20; tc++) s += g_part[(e*20 + tc)*M_ + m];
        g_rinv[e*M_ + m] = 1.0f / fmaxf(sqrtf(s), 1e-8f);
    }
}

// ---------------- TR: transpose + scale + split ------------------------------
__global__ void __launch_bounds__(256)
tr_all(const float* __restrict__ sup, const float* __restrict__ qf) {
    int tc = blockIdx.x;
    int e  = blockIdx.y;
    int tid = threadIdx.x;
    __shared__ float tile[32][201];

    if (e < B_*N_) {
        int bn = e;
        const float* base = sup + (size_t)bn * KS_ * C_ * M_;
        for (int idx = tid; idx < 32*M_; idx += 256) {
            int cc = idx / M_, m = idx - cc*M_;
            float v = 0.f;
            #pragma unroll
            for (int k = 0; k < KS_; k++)
                v += base[(size_t)k*C_*M_ + (size_t)(tc*32 + cc)*M_ + m];
            tile[cc][m] = v * 0.2f;
        }
        __syncthreads();
        size_t ob = (size_t)bn * NPAD * C_;
        const float* rv = g_rinv + e*M_;
        for (int idx = tid; idx < M_*32; idx += 256) {
            int m = idx >> 5, cc = idx & 31;
            float v = tile[cc][m] * rv[m];
            size_t o = ob + (size_t)m*C_ + tc*32 + cc;
            g_sn_hi[o] = __float2half_rn(v);
            g_s32[o] = v;
        }
    } else {
        int bq = e - B_*N_;
        int b = bq / Q_, q = bq % Q_;
        const float* in = qf + (size_t)bq * C_ * M_;
        for (int idx = tid; idx < 32*M_; idx += 256) {
            int cc = idx / M_, m = idx - cc*M_;
            tile[cc][m] = in[(size_t)(tc*32 + cc)*M_ + m];
        }
        __syncthreads();
        size_t rowbase = (size_t)b * RPB + (size_t)q * M_;
        const float* rv = g_rinv + e*M_;
        for (int idx = tid; idx < M_*32; idx += 256) {
            int m = idx >> 5, cc = idx & 31;
            float v = tile[cc][m] * rv[m];
            __half h = __float2half_rn(v);
            size_t o = (rowbase + m)*C_ + tc*32 + cc;
            g_qn_hi[o] = h;
            g_qn_lo[o] = __float2half_rn(v - __half2float(h));
        }
    }
}

// ---------------- fp16 hi-only HMMA GEMM + candidate epilogue ---------------
__global__ void __launch_bounds__(TPB, 4)
gemm_hi() {
    int nh = blockIdx.x;             // n*2 + half
    int n = nh >> 1, half = nh & 1;
    int mt = blockIdx.y, b = blockIdx.z;

    extern __shared__ char dynsm[];
    uint32_t sbase = s2u(dynsm);

    int tid = threadIdx.x, lane = tid & 31, wid = tid >> 5;
    int wr = wid >> 1, wc = wid & 1;

    const size_t arbase = (size_t)b * RPB + (size_t)mt * 64;
    const size_t brbase = (size_t)(b*N_ + n) * NPAD + (size_t)half * 112;

    int rA0 = tid >> 2,          cA0 = tid & 3;
    int itA1 = tid + 128;
    int rA1 = itA1 >> 2,         cA1 = itA1 & 3;
    const size_t gA0 = (arbase + rA0) * C_ + cA0*8;
    const size_t gA1 = (arbase + rA1) * C_ + cA1*8;
    const uint32_t dA0 = rA0*ROWB + cA0*16;
    const uint32_t dA1 = rA1*ROWB + cA1*16;
    int rB0 = tid >> 2,          cB0 = tid & 3;
    int itB1 = tid + 128;
    int rB1 = itB1 >> 2,         cB1 = itB1 & 3;
    int itB2 = tid + 256;
    int rB2 = itB2 >> 2,         cB2 = itB2 & 3;
    int itB3 = tid + 384;
    int rB3 = itB3 >> 2,         cB3 = itB3 & 3;
    const size_t gB0 = (brbase + rB0) * C_ + cB0*8;
    const size_t gB1 = (brbase + rB1) * C_ + cB1*8;
    const size_t gB2 = (brbase + rB2) * C_ + cB2*8;
    const size_t gB3 = (brbase + rB3) * C_ + cB3*8;
    const uint32_t dB0 = rB0*ROWB + cB0*16;
    const uint32_t dB1 = rB1*ROWB + cB1*16;
    const uint32_t dB2 = rB2*ROWB + cB2*16;
    const uint32_t dB3 = rB3*ROWB + cB3*16;
    const bool hasB3 = (tid < 64);

    auto issue = [&](int stage, int kt) {
        uint32_t so = sbase + stage * STAGEB;
        int ko = kt * KC;
        cp16(so + AHI_O + dA0, g_qn_hi + gA0 + ko);
        cp16(so + AHI_O + dA1, g_qn_hi + gA1 + ko);
        cp16(so + BHI_O + dB0, g_sn_hi + gB0 + ko);
        cp16(so + BHI_O + dB1, g_sn_hi + gB1 + ko);
        cp16(so + BHI_O + dB2, g_sn_hi + gB2 + ko);
        if (hasB3) cp16(so + BHI_O + dB3, g_sn_hi + gB3 + ko);
        asm volatile("cp.async.commit_group;" ::: "memory");
    };

    uint32_t aoff[2][2];
    {
        int arow = (lane & 7) + ((lane >> 3) & 1) * 8;
        int acolb = ((lane >> 4) & 1) * 16;
        #pragma unroll
        for (int i = 0; i < 2; i++)
            #pragma unroll
            for (int ks = 0; ks < 2; ks++)
                aoff[i][ks] = (uint32_t)((wr*32 + i*16 + arow)*ROWB + ks*32 + acolb);
    }
    const uint32_t boff0 = (uint32_t)((wc*56 + (lane & 7))*ROWB
                          + ((lane >> 4) & 1)*32 + ((lane >> 3) & 1)*16);

    float acc[2][7][4];
    #pragma unroll
    for (int i = 0; i < 2; i++)
        #pragma unroll
        for (int j = 0; j < 7; j++)
            #pragma unroll
            for (int p = 0; p < 4; p++) acc[i][j][p] = 0.f;

    issue(0, 0);

    #pragma unroll 1
    for (int kt = 0; kt < KT_; kt++) {
        if (kt + 1 < KT_) {
            issue((kt + 1) & 1, kt + 1);
            asm volatile("cp.async.wait_group 1;" ::: "memory");
        } else {
            asm volatile("cp.async.wait_group 0;" ::: "memory");
        }
        __syncthreads();

        uint32_t so = sbase + (kt & 1) * STAGEB;

        uint32_t Ahi[2][2][4];
        #pragma unroll
        for (int i = 0; i < 2; i++)
            #pragma unroll
            for (int ks = 0; ks < 2; ks++)
                ldsm4(Ahi[i][ks], so + AHI_O + aoff[i][ks]);

        uint32_t B4[2][4];
        ldsm4(B4[0], so + BHI_O + boff0);

        #pragma unroll
        for (int j = 0; j < 7; j++) {
            int cur = j & 1;
            if (j < 6)
                ldsm4(B4[cur ^ 1], so + BHI_O + boff0 + (j+1)*(8*ROWB));
            #pragma unroll
            for (int ks = 0; ks < 2; ks++)
                #pragma unroll
                for (int i = 0; i < 2; i++)
                    mma16816f(acc[i][j], Ahi[i][ks], &B4[cur][ks*2]);
        }
        __syncthreads();
    }

    // ---- epilogue: approx max + candidate collection per (row, half) ----
    float*   sv   = (float*)dynsm;                 // [2][64]
    float*   mv   = (float*)(dynsm + 512);         // [64]
    int*     scnt = (int*)(dynsm + 768);           // [64]
    uint8_t* slst = (uint8_t*)(dynsm + 1024);      // [64][8]

    int rq = lane >> 2, cq = lane & 3;
    #pragma unroll
    for (int i = 0; i < 2; i++) {
        #pragma unroll
        for (int rh = 0; rh < 2; rh++) {
            float bv = -1e30f;
            #pragma unroll
            for (int j = 0; j < 7; j++)
                #pragma unroll
                for (int p = 0; p < 2; p++) {
                    int gc = half*112 + wc*56 + j*8 + cq*2 + p;
                    float v = acc[i][j][rh*2 + p];
                    if (gc < M_ && v > bv) bv = v;
                }
            #pragma unroll
            for (int off = 1; off < 4; off <<= 1) {
                float ov = __shfl_xor_sync(0xffffffffu, bv, off);
                if (ov > bv) bv = ov;
            }
            if (cq == 0) {
                int rl = wr*32 + i*16 + rh*8 + rq;
                sv[wc*64 + rl] = bv;
            }
        }
    }
    __syncthreads();
    if (tid < 64) {
        mv[tid] = fmaxf(sv[tid], sv[64 + tid]);
        scnt[tid] = 0;
    }
    __syncthreads();
    #pragma unroll
    for (int i = 0; i < 2; i++) {
        #pragma unroll
        for (int rh = 0; rh < 2; rh++) {
            int rl = wr*32 + i*16 + rh*8 + rq;
            float t = mv[rl] - DELTA2;
            #pragma unroll
            for (int j = 0; j < 7; j++)
                #pragma unroll
                for (int p = 0; p < 2; p++) {
                    int gc = half*112 + wc*56 + j*8 + cq*2 + p;
                    float v = acc[i][j][rh*2 + p];
                    if (gc < M_ && v > t) {
                        int pos = atomicAdd(&scnt[rl], 1);
                        if (pos < 8) slst[rl*8 + pos] = (uint8_t)gc;
                    }
                }
        }
    }
    __syncthreads();
    if (tid < 64) {
        int gr = mt*64 + tid;
        if (gr < Q_*M_) {
            int q = gr / M_, mq = gr % M_;
            int o = (((b*Q_ + q)*N_ + n)*2 + half)*M_ + mq;
            g_hmax[o] = mv[tid];
            g_ccnt[o] = scnt[tid];
            g_cand[o] = *(uint2*)(slst + tid*8);
        }
    }
}

// ---------------- rescore2: 300 fat blocks, qrow in registers ---------------
// Block per bq (512 thr, 16 warps, no smem). Warp w handles mq = w, w+16, ...
// Per mq: reconstruct qrow into regs (20 el/lane, float4-aligned groups),
// then evaluate all 5 classes' candidates (5 LDG.128 per eval).
__global__ void __launch_bounds__(512)
rescore2() {
    int bq = blockIdx.x;
    int b = bq / Q_, q = bq % Q_;
    int tid = threadIdx.x;
    int w = tid >> 5, lane = tid & 31;

    for (int mq = w; mq < M_; mq += 16) {
        // qrow regs: element c = lane*4 + it*128 + j  (it<5, j<4)
        float qr[5][4];
        {
            size_t qb = ((size_t)b * RPB + (size_t)q * M_ + mq) * C_;
            const __half2* h2 = (const __half2*)(g_qn_hi + qb);
            const __half2* l2 = (const __half2*)(g_qn_lo + qb);
            #pragma unroll
            for (int it = 0; it < 5; it++) {
                int e2 = lane*2 + it*64;            // half2 index of element group
                float2 h0 = __half22float2(h2[e2]);
                float2 h1 = __half22float2(h2[e2 + 1]);
                float2 l0 = __half22float2(l2[e2]);
                float2 l1 = __half22float2(l2[e2 + 1]);
                qr[it][0] = h0.x + l0.x;
                qr[it][1] = h0.y + l0.y;
                qr[it][2] = h1.x + l1.x;
                qr[it][3] = h1.y + l1.y;
            }
        }

        #pragma unroll 1
        for (int n = 0; n < N_; n++) {
            int o0 = ((bq*N_ + n)*2 + 0)*M_ + mq;
            int o1 = o0 + M_;
            float m0 = g_hmax[o0], m1 = g_hmax[o1];
            float mg = fmaxf(m0, m1);

            float bv = -1e30f; int bc = 0x7fffffff;
            const size_t snb = (size_t)(b*N_ + n) * NPAD * C_;

            #pragma unroll
            for (int half = 0; half < 2; half++) {
                float mh = half ? m1 : m0;
                if (mh < mg - DELTA2) continue;
                int o = half ? o1 : o0;
                int cnt = g_ccnt[o];

                auto eval = [&](int gc) {
                    const float4* s4 = (const float4*)(g_s32 + snb + (size_t)gc * C_);
                    float s = 0.f;
                    #pragma unroll
                    for (int it = 0; it < 5; it++) {
                        float4 bb = s4[lane + it*32];
                        s += qr[it][0]*bb.x + qr[it][1]*bb.y
                           + qr[it][2]*bb.z + qr[it][3]*bb.w;
                    }
                    #pragma unroll
                    for (int off = 16; off > 0; off >>= 1)
                        s += __shfl_xor_sync(0xffffffffu, s, off);
                    if (s > bv || (s == bv && gc < bc)) { bv = s; bc = gc; }
                };

                if (cnt <= 8) {
                    uint2 pk = g_cand[o];
                    for (int k = 0; k < cnt; k++) {
                        uint32_t w32 = (k < 4) ? pk.x : pk.y;
                        int gc = (w32 >> ((k & 3) * 8)) & 0xFF;
                        eval(gc);
                    }
                } else {                               // overflow: full half scan
                    int lo = half*112;
                    int hi = (lo + 112 < M_) ? lo + 112 : M_;
                    for (int gc = lo; gc < hi; gc++) eval(gc);
                }
            }

            if (lane == 0) {
                int o = (bq*N_ + n)*M_ + mq;
                g_rowmax[o] = bv;
                g_rowarg[o] = bc;
            }
        }
    }
}

// ---------------- per-(b,q) mutual-NN mask + predict + loss -----------------
__global__ void combine_kernel(const int* __restrict__ qy) {
    int bq = blockIdx.x;
    int tid = threadIdx.x;          // 256 threads

    __shared__ float rowm[N_][M_];
    __shared__ float bestv[M_];
    __shared__ int   bestj[M_];
    __shared__ int   maskf[M_];
    __shared__ float pred[N_];

    if (tid < M_) {
        float bv = -1e30f; int bj = 0;
        #pragma unroll
        for (int nn = 0; nn < N_; nn++) {
            int o = (bq*N_ + nn)*M_ + tid;
            float rv = g_rowmax[o];
            int   ra = g_rowarg[o];
            rowm[nn][tid] = rv;
            if (rv > bv) { bv = rv; bj = nn*M_ + ra; }   // ascending n
        }
        bestv[tid] = bv; bestj[tid] = bj;
    }
    __syncthreads();

    if (tid < M_) {
        float v = bestv[tid]; int j = bestj[tid];
        int ok = (v + 1.0f) > 0.0f;
        for (int t = 0; t < M_; t++) {
            if (t == tid) continue;
            if (bestj[t] == j) {
                float vt = bestv[t];
                if (vt > v || (vt == v && t < tid)) ok = 0;
            }
        }
        maskf[tid] = ok;
    }
    __syncthreads();

    if (tid < N_) {
        float s = 0.f;
        for (int m = 0; m < M_; m++)
            if (maskf[m]) s += rowm[tid][m];
        pred[tid] = 2.0f * s;       // TEMPERATURE
    }
    __syncthreads();

    if (tid == 0) {
        float mx = pred[0];
        #pragma unroll
        for (int nn = 1; nn < N_; nn++) mx = fmaxf(mx, pred[nn]);
        float se = 0.f;
        #pragma unroll
        for (int nn = 0; nn < N_; nn++) se += expf(pred[nn] - mx);
        float lse = mx + logf(se);
        int y = qy[bq];
        g_loss[bq] = lse - pred[y];
    }
}

__global__ void final_kernel(float* __restrict__ out) {
    __shared__ float part[32];
    int lane = threadIdx.x;
    float s = 0.f;
    for (int i = lane; i < BQ_; i += 32) s += g_loss[i];
    part[lane] = s;
    __syncwarp();
    if (lane == 0) {
        float t = 0.f;
        #pragma unroll
        for (int w = 0; w < 32; w++) t += part[w];
        out[0] = t / (float)BQ_;
    }
}

extern "C" void kernel_launch(void* const* d_in, const int* in_sizes, int n_in,
                              void* d_out, int out_size) {
    const float* sup = (const float*)d_in[0];
    // d_in[1] = support_y : unused by the reference computation
    const float* qf  = (const float*)d_in[2];
    const int*   qy  = (const int*)d_in[3];

    cudaFuncSetAttribute(gemm_hi, cudaFuncAttributeMaxDynamicSharedMemorySize, SMEM_BYTES);

    part_sumsq<<<dim3(20, NE_), 256>>>(sup, qf);      // launch 0
    rinv_k    <<<NE_, 224>>>();                       // launch 1
    tr_all    <<<dim3(20, NE_), 256>>>(sup, qf);      // launch 2

    dim3 grid(N_*2, MT_, B_);
    gemm_hi<<<grid, TPB, SMEM_BYTES>>>();             // launch 3 (ncu slot)

    rescore2<<<BQ_, 512>>>();                         // launch 4
    combine_kernel<<<BQ_, 256>>>(qy);                 // launch 5
    final_kernel  <<<1, 32>>>((float*)d_out);         // launch 6
}